// round 13
// baseline (speedup 1.0000x reference)
#include <cuda_runtime.h>
#include <cuda_fp16.h>
#include <cstdint>

#define IN_CH 512
#define BATCH 8
#define HH 100
#define WW 100
#define NA 9
#define NHEAD 45
#define NHEADP 48
#define NPOSOUT 80000                // BATCH*HH*WW

#define TPB 2500                     // 50x50 2x2-output tiles per batch
#define NTILES 20000                 // BATCH * TPB
#define TPAD 20096                   // 157 * 128 (tile-dim padded for staging)

#define BM 128                       // co per CTA
#define BN 128                       // tiles per CTA
#define TBLK 157                     // ceil(NTILES/BN)

// GEMM smem: 3 stages x (Whi 16K | Xhi 16K)
#define OFF_WHI 0
#define OFF_XHI 16384
#define STAGE_BYTES 32768
#define NSTAGE 3
#define GEMM_SMEM (NSTAGE * STAGE_BYTES)     // 98304
#define XS_SMEM (4 * 32 * 105 * 4)           // 53760
#define HEADS_SMEM (512 * 24 * 8)            // 98304

// ---------------- device scratch (allocation-free) ----------------
__device__ float g_feat[BATCH * IN_CH * HH * WW];               // fp32 feature map
__device__ __half g_xthi[(size_t)16 * TPAD * IN_CH];            // winograd input (fp16)
__device__ __half g_wthi[(size_t)16 * IN_CH * IN_CH];           // winograd weights [u][co][ci]
__device__ float g_M[(size_t)8 * IN_CH * TPAD];                 // r-folded products [s*2+h][co][tile]
__device__ float g_wh[IN_CH * NHEADP];                          // head weights [ci][co48]

extern __shared__ char dsm_raw[];

// ---------------- PTX helpers ----------------
__device__ __forceinline__ uint32_t smem_u32(const void* p) {
    uint32_t a;
    asm("{ .reg .u64 t; cvta.to.shared.u64 t, %1; cvt.u32.u64 %0, t; }" : "=r"(a) : "l"(p));
    return a;
}
__device__ __forceinline__ void cp16(uint32_t sdst, const void* gsrc) {
    asm volatile("cp.async.cg.shared.global [%0], [%1], 16;" :: "r"(sdst), "l"(gsrc) : "memory");
}
#define CP_COMMIT() asm volatile("cp.async.commit_group;" ::: "memory")
#define CP_WAIT(n)  asm volatile("cp.async.wait_group %0;" :: "n"(n) : "memory")

__device__ __forceinline__ void ldsm4(uint32_t* r, uint32_t addr) {
    asm volatile("ldmatrix.sync.aligned.m8n8.x4.shared.b16 {%0,%1,%2,%3}, [%4];"
        : "=r"(r[0]), "=r"(r[1]), "=r"(r[2]), "=r"(r[3]) : "r"(addr));
}
__device__ __forceinline__ void mma_f32(float* d, const uint32_t* a, const uint32_t* b) {
    asm volatile(
        "mma.sync.aligned.m16n8k16.row.col.f32.f16.f16.f32 "
        "{%0,%1,%2,%3}, {%4,%5,%6,%7}, {%8,%9}, {%0,%1,%2,%3};"
        : "+f"(d[0]), "+f"(d[1]), "+f"(d[2]), "+f"(d[3])
        : "r"(a[0]), "r"(a[1]), "r"(a[2]), "r"(a[3]), "r"(b[0]), "r"(b[1]));
}
__device__ __forceinline__ uint32_t swz(uint32_t off) { return off ^ ((off >> 3) & 0x70); }

// packed fp32x2 (verified R2/R12)
__device__ __forceinline__ unsigned long long pk2(float x, float y) {
    unsigned long long r;
    asm("mov.b64 %0, {%1, %2};" : "=l"(r) : "r"(__float_as_int(x)), "r"(__float_as_int(y)));
    return r;
}
__device__ __forceinline__ void upk2(unsigned long long v, float& x, float& y) {
    int a, b;
    asm("mov.b64 {%0, %1}, %2;" : "=r"(a), "=r"(b) : "l"(v));
    x = __int_as_float(a); y = __int_as_float(b);
}
__device__ __forceinline__ void fma2(unsigned long long& d, unsigned long long a, unsigned long long b) {
    asm("fma.rn.f32x2 %0, %1, %2, %0;" : "+l"(d) : "l"(a), "l"(b));
}

// ---------------- weight winograd transform (unchanged from R12) ----------------
__global__ void wt_kernel(const float* __restrict__ w) {
    int idx = blockIdx.x * blockDim.x + threadIdx.x;
    if (idx >= IN_CH * IN_CH) return;
    int co = idx / IN_CH, ci = idx % IN_CH;
    const float* wp = w + (size_t)idx * 9;
    float a[3][3];
    #pragma unroll
    for (int r = 0; r < 3; r++)
        #pragma unroll
        for (int c = 0; c < 3; c++) a[r][c] = wp[r * 3 + c];
    float u[4][3];
    #pragma unroll
    for (int c = 0; c < 3; c++) {
        u[0][c] = a[0][c];
        u[1][c] = 0.5f * (a[0][c] + a[1][c] + a[2][c]);
        u[2][c] = 0.5f * (a[0][c] - a[1][c] + a[2][c]);
        u[3][c] = a[2][c];
    }
    #pragma unroll
    for (int r = 0; r < 4; r++) {
        float t0 = u[r][0], t1 = u[r][1], t2 = u[r][2];
        float v[4] = { t0, 0.5f * (t0 + t1 + t2), 0.5f * (t0 - t1 + t2), t2 };
        #pragma unroll
        for (int s = 0; s < 4; s++)
            g_wthi[((size_t)(r * 4 + s) * IN_CH + co) * IN_CH + ci] = __float2half_rn(v[s]);
    }
}

__global__ void transform_whead(const float* __restrict__ wcls, const float* __restrict__ wbbox) {
    int idx = blockIdx.x * blockDim.x + threadIdx.x;
    if (idx >= IN_CH * NHEADP) return;
    int co = idx % NHEADP, ci = idx / NHEADP;
    float v = 0.0f;
    if (co < NA)         v = wcls[co * IN_CH + ci];
    else if (co < NHEAD) v = wbbox[(co - NA) * IN_CH + ci];
    g_wh[idx] = v;
}

// ---------------- FUSED input transform: x (NCHW) -> B^T d B -> g_xthi ----------------
// grid (50 ty, 16 ci-groups, 8 b), 256 threads; smem = 4 rows x 32 ci x 105 px
__global__ __launch_bounds__(256)
void xsplit_fused(const float* __restrict__ x) {
    float (*s_d)[32][105] = (float(*)[32][105])dsm_raw;
    const int ty = blockIdx.x;
    const int cg = blockIdx.y;
    const int b  = blockIdx.z;
    const int tid = threadIdx.x;

    // load 4 rows (y = 2ty-1 .. 2ty+2) x 100 x x 32 ci, coalesced; zero OOB rows
    for (int e = tid; e < 4 * 32 * 100; e += 256) {
        const int x_   = e % 100;
        const int ci32 = (e / 100) % 32;
        const int r    = e / 3200;
        const int y    = 2 * ty - 1 + r;
        float v = 0.0f;
        if (y >= 0 && y < HH)
            v = x[(((size_t)b * IN_CH + cg * 32 + ci32) * HH + y) * WW + x_];
        s_d[r][ci32][x_ + 1] = v;
    }
    // zero padded columns px = 0 and 101 (4r x 32ci x 2 = 256 = blockDim)
    {
        const int r    = tid >> 6;
        const int ci32 = (tid >> 1) & 31;
        const int px   = (tid & 1) ? 101 : 0;
        s_d[r][ci32][px] = 0.0f;
    }
    __syncthreads();

    // compute: item = (tx, ci); same fp32 op order as R12's verified xt (bit-identical)
    for (int it = tid; it < 50 * 32; it += 256) {
        const int tx   = it >> 5;
        const int ci32 = it & 31;
        const int ci   = cg * 32 + ci32;
        const int tile = b * TPB + ty * 50 + tx;

        float d[4][4];
        #pragma unroll
        for (int r = 0; r < 4; r++)
            #pragma unroll
            for (int c = 0; c < 4; c++)
                d[r][c] = s_d[r][ci32][2 * tx + c];

        float t[4][4];
        #pragma unroll
        for (int c = 0; c < 4; c++) {
            t[0][c] = d[0][c] - d[2][c];
            t[1][c] = d[1][c] + d[2][c];
            t[2][c] = d[2][c] - d[1][c];
            t[3][c] = d[1][c] - d[3][c];
        }
        #pragma unroll
        for (int r = 0; r < 4; r++) {
            float v[4];
            v[0] = t[r][0] - t[r][2];
            v[1] = t[r][1] + t[r][2];
            v[2] = t[r][2] - t[r][1];
            v[3] = t[r][1] - t[r][3];
            #pragma unroll
            for (int s = 0; s < 4; s++)
                g_xthi[((size_t)(r * 4 + s) * TPAD + tile) * IN_CH + ci] = __float2half_rn(v[s]);
        }
    }
}

// ---------------- GEMM with in-register r-fold: grid.z = s, loop r ----------------
__global__ __launch_bounds__(256, 1)
void gemm_mma() {
    const uint32_t base = smem_u32(dsm_raw);
    const int tid  = threadIdx.x;
    const int lane = tid & 31;
    const int wid  = tid >> 5;
    const int wm   = wid & 1;
    const int wn   = wid >> 1;
    const int co0  = blockIdx.x * BM;
    const int p0   = blockIdx.y * BN;
    const int s_blk = blockIdx.z;

    float accM[4][4][4], t0[4][4][4], t1[4][4][4];
    #pragma unroll
    for (int mt = 0; mt < 4; mt++)
        #pragma unroll
        for (int nt = 0; nt < 4; nt++)
            #pragma unroll
            for (int i = 0; i < 4; i++) {
                accM[mt][nt][i] = 0.0f; t0[mt][nt][i] = 0.0f; t1[mt][nt][i] = 0.0f;
            }

    const int arowoff = lane & 15;
    const int ahalf   = lane >> 4;
    const int browoff = (lane & 7) + ((lane >> 4) << 3);
    const int bhalf   = (lane >> 3) & 1;
    const int l7      = lane & 7;

    uint32_t aoff[4];
    #pragma unroll
    for (int mt = 0; mt < 4; mt++) aoff[mt] = (uint32_t)(wm * 64 + mt * 16 + arowoff) * 128u;
    uint32_t boff[2];
    #pragma unroll
    for (int np = 0; np < 2; np++) boff[np] = (uint32_t)(wn * 32 + np * 16 + browoff) * 128u;

    auto stage = [&](int chunk, uint32_t sb) {
        const int u  = ((chunk >> 3) << 2) + s_blk;      // u = r*4 + s
        const int kc = chunk & 7;
        const __half* whi = g_wthi + (size_t)u * IN_CH * IN_CH;
        const __half* xhi = g_xthi + (size_t)u * TPAD * IN_CH;
        #pragma unroll
        for (int i = 0; i < 4; i++) {
            int e = i * 256 + tid;
            int rr = e >> 3, cc = e & 7;
            uint32_t so = swz((uint32_t)(rr * 128 + cc * 16));
            size_t gw = (size_t)(co0 + rr) * IN_CH + kc * 64 + cc * 8;
            size_t gx = (size_t)(p0 + rr) * IN_CH + kc * 64 + cc * 8;
            cp16(sb + OFF_WHI + so, whi + gw);
            cp16(sb + OFF_XHI + so, xhi + gx);
        }
        CP_COMMIT();
    };

    stage(0, base);
    stage(1, base + STAGE_BYTES);

    #pragma unroll 1
    for (int chunk = 0; chunk < 32; chunk++) {
        if (chunk + 2 < 32) { CP_WAIT(1); } else { CP_WAIT(0); }
        __syncthreads();
        if (chunk + 2 < 32)
            stage(chunk + 2, base + (uint32_t)((chunk + 2) % NSTAGE) * STAGE_BYTES);

        const uint32_t sb = base + (uint32_t)(chunk % NSTAGE) * STAGE_BYTES;
        #pragma unroll
        for (int ks = 0; ks < 4; ks++) {
            const uint32_t acol = (uint32_t)((2 * ks + ahalf) ^ l7) << 4;
            const uint32_t bcol = (uint32_t)((2 * ks + bhalf) ^ l7) << 4;
            uint32_t ah[4][4], bh[2][4];
            #pragma unroll
            for (int mt = 0; mt < 4; mt++)
                ldsm4(ah[mt], sb + OFF_WHI + aoff[mt] + acol);
            #pragma unroll
            for (int np = 0; np < 2; np++)
                ldsm4(bh[np], sb + OFF_XHI + boff[np] + bcol);
            #pragma unroll
            for (int mt = 0; mt < 4; mt++)
                #pragma unroll
                for (int nt = 0; nt < 4; nt++)
                    mma_f32(accM[mt][nt], ah[mt], &bh[nt >> 1][(nt & 1) * 2]);
        }

        // r complete: fold A^T over r in original inv order (t0 = m0+m1+m2; t1 = m1-m2-m3)
        if ((chunk & 7) == 7) {
            const int r = chunk >> 3;
            #pragma unroll
            for (int mt = 0; mt < 4; mt++)
                #pragma unroll
                for (int nt = 0; nt < 4; nt++)
                    #pragma unroll
                    for (int i = 0; i < 4; i++) {
                        const float m = accM[mt][nt][i];
                        if (r < 3)  t0[mt][nt][i] += m;
                        if (r == 1) t1[mt][nt][i] += m;
                        if (r >= 2) t1[mt][nt][i] -= m;
                        accM[mt][nt][i] = 0.0f;
                    }
        }
    }

    // epilogue: write t0 (h=0) and t1 (h=1) planes
    #pragma unroll
    for (int mt = 0; mt < 4; mt++) {
        const int r0 = co0 + wm * 64 + mt * 16 + (lane >> 2);
        const size_t h0 = ((size_t)(s_blk * 2 + 0) * IN_CH + r0) * TPAD;
        const size_t h1 = ((size_t)(s_blk * 2 + 1) * IN_CH + r0) * TPAD;
        #pragma unroll
        for (int nt = 0; nt < 4; nt++) {
            const int p = p0 + wn * 32 + nt * 8 + ((lane & 3) << 1);
            *(float2*)&g_M[h0 + p]            = make_float2(t0[mt][nt][0], t0[mt][nt][1]);
            *(float2*)&g_M[h0 + 8 * TPAD + p] = make_float2(t0[mt][nt][2], t0[mt][nt][3]);
            *(float2*)&g_M[h1 + p]            = make_float2(t1[mt][nt][0], t1[mt][nt][1]);
            *(float2*)&g_M[h1 + 8 * TPAD + p] = make_float2(t1[mt][nt][2], t1[mt][nt][3]);
        }
    }
}

// ---------------- inverse transform (s-direction only; r pre-folded) ----------------
__global__ __launch_bounds__(256)
void inv_kernel(const float* __restrict__ brpn) {
    const int idx = blockIdx.x * 256 + threadIdx.x;
    if (idx >= IN_CH * NTILES) return;
    const int co   = idx / NTILES;
    const int tile = idx - co * NTILES;
    const int b  = tile / TPB;
    const int t2 = tile - b * TPB;
    const int ty = t2 / 50;
    const int tx = t2 - ty * 50;

    float n[4][2];
    #pragma unroll
    for (int s = 0; s < 4; s++)
        #pragma unroll
        for (int h = 0; h < 2; h++)
            n[s][h] = g_M[((size_t)(s * 2 + h) * IN_CH + co) * TPAD + tile];

    const float bv = brpn[co];
    float o00 = n[0][0] + n[1][0] + n[2][0] + bv;
    float o01 = n[1][0] - n[2][0] - n[3][0] + bv;
    float o10 = n[0][1] + n[1][1] + n[2][1] + bv;
    float o11 = n[1][1] - n[2][1] - n[3][1] + bv;

    float* fb = g_feat + ((size_t)(b * IN_CH + co)) * (HH * WW) + (size_t)(2 * ty) * WW + 2 * tx;
    *(float2*)fb        = make_float2(fmaxf(o00, 0.0f), fmaxf(o01, 0.0f));
    *(float2*)(fb + WW) = make_float2(fmaxf(o10, 0.0f), fmaxf(o11, 0.0f));
}

// ---------------- FUSED heads: single kernel, FFMA2 co-pairs, full 512-ci loop ----------------
__global__ __launch_bounds__(256)
void heads_kernel(const float* __restrict__ bcls, const float* __restrict__ bbbox,
                  float* __restrict__ out) {
    unsigned long long (*sw2)[24] = (unsigned long long(*)[24])dsm_raw;
    const int idx = blockIdx.x * 256 + threadIdx.x;

    for (int e = threadIdx.x; e < 512 * 24; e += 256)
        ((unsigned long long*)dsm_raw)[e] = ((const unsigned long long*)g_wh)[e];
    __syncthreads();

    if (idx >= NPOSOUT) return;
    const int b = idx / (HH * WW);
    const int hw = idx % (HH * WW);
    const float* fp = g_feat + (size_t)b * IN_CH * (HH * WW) + hw;

    unsigned long long acc[24];
    #pragma unroll
    for (int q = 0; q < 24; q++) acc[q] = 0ull;

    #pragma unroll 2
    for (int ci = 0; ci < IN_CH; ci++) {
        float v = fp[(size_t)ci * (HH * WW)];
        unsigned long long vv = pk2(v, v);
        const unsigned long long* wr = sw2[ci];
        #pragma unroll
        for (int q = 0; q < 24; q++) fma2(acc[q], vv, wr[q]);
    }

    float s[48];
    #pragma unroll
    for (int q = 0; q < 24; q++) upk2(acc[q], s[2 * q], s[2 * q + 1]);

    #pragma unroll
    for (int co = 0; co < NA; co++)
        out[((size_t)(b * NA + co)) * (HH * WW) + hw] = s[co] + bcls[co];
    float* outb = out + (size_t)BATCH * NA * (HH * WW);
    #pragma unroll
    for (int j = 0; j < 36; j++)
        outb[((size_t)(b * 36 + j)) * (HH * WW) + hw] = s[NA + j] + bbbox[j];
}

// ---------------- launch ----------------
extern "C" void kernel_launch(void* const* d_in, const int* in_sizes, int n_in,
                              void* d_out, int out_size) {
    const float* x      = (const float*)d_in[0];
    const float* w_rpn  = (const float*)d_in[1];
    const float* b_rpn  = (const float*)d_in[2];
    const float* w_cls  = (const float*)d_in[3];
    const float* b_cls  = (const float*)d_in[4];
    const float* w_bbox = (const float*)d_in[5];
    const float* b_bbox = (const float*)d_in[6];
    float* out = (float*)d_out;

    cudaFuncSetAttribute(gemm_mma,     cudaFuncAttributeMaxDynamicSharedMemorySize, GEMM_SMEM);
    cudaFuncSetAttribute(xsplit_fused, cudaFuncAttributeMaxDynamicSharedMemorySize, XS_SMEM);
    cudaFuncSetAttribute(heads_kernel, cudaFuncAttributeMaxDynamicSharedMemorySize, HEADS_SMEM);

    wt_kernel<<<(IN_CH * IN_CH + 255) / 256, 256>>>(w_rpn);
    transform_whead<<<(IN_CH * NHEADP + 255) / 256, 256>>>(w_cls, w_bbox);
    xsplit_fused<<<dim3(50, 16, BATCH), 256, XS_SMEM>>>(x);

    gemm_mma<<<dim3(IN_CH / BM, TBLK, 4), 256, GEMM_SMEM>>>();

    inv_kernel<<<(IN_CH * NTILES + 255) / 256, 256>>>(b_rpn);

    heads_kernel<<<(NPOSOUT + 255) / 256, 256, HEADS_SMEM>>>(b_cls, b_bbox, out);
}

// round 14
// speedup vs baseline: 1.1207x; 1.1207x over previous
#include <cuda_runtime.h>
#include <cuda_fp16.h>
#include <cstdint>

#define IN_CH 512
#define BATCH 8
#define HH 100
#define WW 100
#define NA 9
#define NHEAD 45
#define NHEADP 48
#define NPOSOUT 80000                // BATCH*HH*WW

#define TPB 2500                     // 50x50 2x2-output tiles per batch
#define NTILES 20000                 // BATCH * TPB
#define TPAD 20096                   // 157 * 128 (tile-dim padded for staging)
#define NU 16                        // winograd coordinates (4x4)

#define BM 128                       // co per CTA
#define BN 128                       // tiles per CTA
#define TBLK 157                     // ceil(NTILES/BN)
#define NITER 8                      // 512 ci / 64

// GEMM smem: 3 stages x (Whi 16K | Xhi 16K)
#define OFF_WHI 0
#define OFF_XHI 16384
#define STAGE_BYTES 32768
#define NSTAGE 3
#define GEMM_SMEM (NSTAGE * STAGE_BYTES)     // 98304
#define XS_SMEM (4 * 32 * 105 * 4)           // 53760
#define HEADS_SMEM (512 * 24 * 8)            // 98304

// ---------------- device scratch (allocation-free) ----------------
__device__ float g_feat[BATCH * IN_CH * HH * WW];               // fp32 feature map
__device__ __half g_xthi[(size_t)NU * TPAD * IN_CH];            // winograd input (fp16)
__device__ __half g_wthi[(size_t)NU * IN_CH * IN_CH];           // winograd weights [u][co][ci]
__device__ float g_M[(size_t)NU * IN_CH * TPAD];                // transformed-domain products
__device__ float g_wh[IN_CH * NHEADP];                          // head weights [ci][co48]

extern __shared__ char dsm_raw[];

// ---------------- PTX helpers ----------------
__device__ __forceinline__ uint32_t smem_u32(const void* p) {
    uint32_t a;
    asm("{ .reg .u64 t; cvta.to.shared.u64 t, %1; cvt.u32.u64 %0, t; }" : "=r"(a) : "l"(p));
    return a;
}
__device__ __forceinline__ void cp16(uint32_t sdst, const void* gsrc) {
    asm volatile("cp.async.cg.shared.global [%0], [%1], 16;" :: "r"(sdst), "l"(gsrc) : "memory");
}
#define CP_COMMIT() asm volatile("cp.async.commit_group;" ::: "memory")
#define CP_WAIT(n)  asm volatile("cp.async.wait_group %0;" :: "n"(n) : "memory")

__device__ __forceinline__ void ldsm4(uint32_t* r, uint32_t addr) {
    asm volatile("ldmatrix.sync.aligned.m8n8.x4.shared.b16 {%0,%1,%2,%3}, [%4];"
        : "=r"(r[0]), "=r"(r[1]), "=r"(r[2]), "=r"(r[3]) : "r"(addr));
}
__device__ __forceinline__ void mma_f32(float* d, const uint32_t* a, const uint32_t* b) {
    asm volatile(
        "mma.sync.aligned.m16n8k16.row.col.f32.f16.f16.f32 "
        "{%0,%1,%2,%3}, {%4,%5,%6,%7}, {%8,%9}, {%0,%1,%2,%3};"
        : "+f"(d[0]), "+f"(d[1]), "+f"(d[2]), "+f"(d[3])
        : "r"(a[0]), "r"(a[1]), "r"(a[2]), "r"(a[3]), "r"(b[0]), "r"(b[1]));
}
__device__ __forceinline__ uint32_t swz(uint32_t off) { return off ^ ((off >> 3) & 0x70); }

// packed fp32x2 (verified R2/R12)
__device__ __forceinline__ unsigned long long pk2(float x, float y) {
    unsigned long long r;
    asm("mov.b64 %0, {%1, %2};" : "=l"(r) : "r"(__float_as_int(x)), "r"(__float_as_int(y)));
    return r;
}
__device__ __forceinline__ void upk2(unsigned long long v, float& x, float& y) {
    int a, b;
    asm("mov.b64 {%0, %1}, %2;" : "=r"(a), "=r"(b) : "l"(v));
    x = __int_as_float(a); y = __int_as_float(b);
}
__device__ __forceinline__ void fma2(unsigned long long& d, unsigned long long a, unsigned long long b) {
    asm("fma.rn.f32x2 %0, %1, %2, %0;" : "+l"(d) : "l"(a), "l"(b));
}

// ---------------- weight winograd transform (unchanged, verified R10-R13) ----------------
__global__ void wt_kernel(const float* __restrict__ w) {
    int idx = blockIdx.x * blockDim.x + threadIdx.x;
    if (idx >= IN_CH * IN_CH) return;
    int co = idx / IN_CH, ci = idx % IN_CH;
    const float* wp = w + (size_t)idx * 9;
    float a[3][3];
    #pragma unroll
    for (int r = 0; r < 3; r++)
        #pragma unroll
        for (int c = 0; c < 3; c++) a[r][c] = wp[r * 3 + c];
    float u[4][3];
    #pragma unroll
    for (int c = 0; c < 3; c++) {
        u[0][c] = a[0][c];
        u[1][c] = 0.5f * (a[0][c] + a[1][c] + a[2][c]);
        u[2][c] = 0.5f * (a[0][c] - a[1][c] + a[2][c]);
        u[3][c] = a[2][c];
    }
    #pragma unroll
    for (int r = 0; r < 4; r++) {
        float t0 = u[r][0], t1 = u[r][1], t2 = u[r][2];
        float v[4] = { t0, 0.5f * (t0 + t1 + t2), 0.5f * (t0 - t1 + t2), t2 };
        #pragma unroll
        for (int s = 0; s < 4; s++)
            g_wthi[((size_t)(r * 4 + s) * IN_CH + co) * IN_CH + ci] = __float2half_rn(v[s]);
    }
}

__global__ void transform_whead(const float* __restrict__ wcls, const float* __restrict__ wbbox) {
    int idx = blockIdx.x * blockDim.x + threadIdx.x;
    if (idx >= IN_CH * NHEADP) return;
    int co = idx % NHEADP, ci = idx / NHEADP;
    float v = 0.0f;
    if (co < NA)         v = wcls[co * IN_CH + ci];
    else if (co < NHEAD) v = wbbox[(co - NA) * IN_CH + ci];
    g_wh[idx] = v;
}

// ---------------- FUSED input transform (verified R13): x (NCHW) -> B^T d B -> g_xthi ----------------
// grid (50 ty, 16 ci-groups, 8 b), 256 threads; smem = 4 rows x 32 ci x 105 px
__global__ __launch_bounds__(256)
void xsplit_fused(const float* __restrict__ x) {
    float (*s_d)[32][105] = (float(*)[32][105])dsm_raw;
    const int ty = blockIdx.x;
    const int cg = blockIdx.y;
    const int b  = blockIdx.z;
    const int tid = threadIdx.x;

    for (int e = tid; e < 4 * 32 * 100; e += 256) {
        const int x_   = e % 100;
        const int ci32 = (e / 100) % 32;
        const int r    = e / 3200;
        const int y    = 2 * ty - 1 + r;
        float v = 0.0f;
        if (y >= 0 && y < HH)
            v = x[(((size_t)b * IN_CH + cg * 32 + ci32) * HH + y) * WW + x_];
        s_d[r][ci32][x_ + 1] = v;
    }
    {
        const int r    = tid >> 6;
        const int ci32 = (tid >> 1) & 31;
        const int px   = (tid & 1) ? 101 : 0;
        s_d[r][ci32][px] = 0.0f;
    }
    __syncthreads();

    for (int it = tid; it < 50 * 32; it += 256) {
        const int tx   = it >> 5;
        const int ci32 = it & 31;
        const int ci   = cg * 32 + ci32;
        const int tile = b * TPB + ty * 50 + tx;

        float d[4][4];
        #pragma unroll
        for (int r = 0; r < 4; r++)
            #pragma unroll
            for (int c = 0; c < 4; c++)
                d[r][c] = s_d[r][ci32][2 * tx + c];

        float t[4][4];
        #pragma unroll
        for (int c = 0; c < 4; c++) {
            t[0][c] = d[0][c] - d[2][c];
            t[1][c] = d[1][c] + d[2][c];
            t[2][c] = d[2][c] - d[1][c];
            t[3][c] = d[1][c] - d[3][c];
        }
        #pragma unroll
        for (int r = 0; r < 4; r++) {
            float v[4];
            v[0] = t[r][0] - t[r][2];
            v[1] = t[r][1] + t[r][2];
            v[2] = t[r][2] - t[r][1];
            v[3] = t[r][1] - t[r][3];
            #pragma unroll
            for (int s = 0; s < 4; s++)
                g_xthi[((size_t)(r * 4 + s) * TPAD + tile) * IN_CH + ci] = __float2half_rn(v[s]);
        }
    }
}

// ---------------- winograd-domain GEMM (bit-exact revert to passing R12) ----------------
__global__ __launch_bounds__(256, 2)
void gemm_mma() {
    const uint32_t base = smem_u32(dsm_raw);
    const int tid  = threadIdx.x;
    const int lane = tid & 31;
    const int wid  = tid >> 5;
    const int wm   = wid & 1;
    const int wn   = wid >> 1;
    const int co0  = blockIdx.x * BM;
    const int p0   = blockIdx.y * BN;
    const int u    = blockIdx.z;

    float acc[4][4][4];
    #pragma unroll
    for (int mt = 0; mt < 4; mt++)
        #pragma unroll
        for (int nt = 0; nt < 4; nt++)
            #pragma unroll
            for (int i = 0; i < 4; i++) acc[mt][nt][i] = 0.0f;

    const int arowoff = lane & 15;
    const int ahalf   = lane >> 4;
    const int browoff = (lane & 7) + ((lane >> 4) << 3);
    const int bhalf   = (lane >> 3) & 1;
    const int l7      = lane & 7;

    uint32_t aoff[4];
    #pragma unroll
    for (int mt = 0; mt < 4; mt++) aoff[mt] = (uint32_t)(wm * 64 + mt * 16 + arowoff) * 128u;
    uint32_t boff[2];
    #pragma unroll
    for (int np = 0; np < 2; np++) boff[np] = (uint32_t)(wn * 32 + np * 16 + browoff) * 128u;

    const __half* whi = g_wthi + (size_t)u * IN_CH * IN_CH;
    const __half* xhi = g_xthi + (size_t)u * TPAD * IN_CH;

    auto stage = [&](int kc, uint32_t sb) {
        #pragma unroll
        for (int i = 0; i < 4; i++) {
            int e = i * 256 + tid;
            int rr = e >> 3, cc = e & 7;
            uint32_t so = swz((uint32_t)(rr * 128 + cc * 16));
            size_t gw = (size_t)(co0 + rr) * IN_CH + kc * 64 + cc * 8;
            size_t gx = (size_t)(p0 + rr) * IN_CH + kc * 64 + cc * 8;
            cp16(sb + OFF_WHI + so, whi + gw);
            cp16(sb + OFF_XHI + so, xhi + gx);
        }
        CP_COMMIT();
    };

    stage(0, base);
    stage(1, base + STAGE_BYTES);

    for (int c = 0; c < NITER; c++) {
        if (c + 2 < NITER) { CP_WAIT(1); } else { CP_WAIT(0); }
        __syncthreads();
        if (c + 2 < NITER)
            stage(c + 2, base + (uint32_t)((c + 2) % NSTAGE) * STAGE_BYTES);

        const uint32_t sb = base + (uint32_t)(c % NSTAGE) * STAGE_BYTES;
        #pragma unroll
        for (int ks = 0; ks < 4; ks++) {
            const uint32_t acol = (uint32_t)((2 * ks + ahalf) ^ l7) << 4;
            const uint32_t bcol = (uint32_t)((2 * ks + bhalf) ^ l7) << 4;
            uint32_t ah[4][4], bh[2][4];
            #pragma unroll
            for (int mt = 0; mt < 4; mt++)
                ldsm4(ah[mt], sb + OFF_WHI + aoff[mt] + acol);
            #pragma unroll
            for (int np = 0; np < 2; np++)
                ldsm4(bh[np], sb + OFF_XHI + boff[np] + bcol);
            #pragma unroll
            for (int mt = 0; mt < 4; mt++)
                #pragma unroll
                for (int nt = 0; nt < 4; nt++)
                    mma_f32(acc[mt][nt], ah[mt], &bh[nt >> 1][(nt & 1) * 2]);
        }
    }

    #pragma unroll
    for (int mt = 0; mt < 4; mt++) {
        const int r0 = co0 + wm * 64 + mt * 16 + (lane >> 2);
        const size_t mb0 = ((size_t)u * IN_CH + r0) * TPAD;
        const size_t mb1 = ((size_t)u * IN_CH + r0 + 8) * TPAD;
        #pragma unroll
        for (int nt = 0; nt < 4; nt++) {
            const int p = p0 + wn * 32 + nt * 8 + ((lane & 3) << 1);
            *(float2*)&g_M[mb0 + p] = make_float2(acc[mt][nt][0], acc[mt][nt][1]);
            *(float2*)&g_M[mb1 + p] = make_float2(acc[mt][nt][2], acc[mt][nt][3]);
        }
    }
}

// ---------------- inverse transform (bit-exact revert to passing R12) ----------------
__global__ __launch_bounds__(256)
void inv_kernel(const float* __restrict__ brpn) {
    const int idx = blockIdx.x * 256 + threadIdx.x;
    if (idx >= IN_CH * NTILES) return;
    const int co   = idx / NTILES;
    const int tile = idx - co * NTILES;
    const int b  = tile / TPB;
    const int t2 = tile - b * TPB;
    const int ty = t2 / 50;
    const int tx = t2 - ty * 50;

    float m[4][4];
    #pragma unroll
    for (int r = 0; r < 4; r++)
        #pragma unroll
        for (int s = 0; s < 4; s++)
            m[r][s] = g_M[((size_t)(r * 4 + s) * IN_CH + co) * TPAD + tile];

    float t0[4], t1[4];
    #pragma unroll
    for (int s = 0; s < 4; s++) {
        t0[s] = m[0][s] + m[1][s] + m[2][s];
        t1[s] = m[1][s] - m[2][s] - m[3][s];
    }
    const float bv = brpn[co];
    float o00 = t0[0] + t0[1] + t0[2] + bv;
    float o01 = t0[1] - t0[2] - t0[3] + bv;
    float o10 = t1[0] + t1[1] + t1[2] + bv;
    float o11 = t1[1] - t1[2] - t1[3] + bv;

    float* fb = g_feat + ((size_t)(b * IN_CH + co)) * (HH * WW) + (size_t)(2 * ty) * WW + 2 * tx;
    *(float2*)fb        = make_float2(fmaxf(o00, 0.0f), fmaxf(o01, 0.0f));
    *(float2*)(fb + WW) = make_float2(fmaxf(o10, 0.0f), fmaxf(o11, 0.0f));
}

// ---------------- FUSED heads (verified R13): single kernel, FFMA2 co-pairs ----------------
__global__ __launch_bounds__(256)
void heads_kernel(const float* __restrict__ bcls, const float* __restrict__ bbbox,
                  float* __restrict__ out) {
    unsigned long long (*sw2)[24] = (unsigned long long(*)[24])dsm_raw;
    const int idx = blockIdx.x * 256 + threadIdx.x;

    for (int e = threadIdx.x; e < 512 * 24; e += 256)
        ((unsigned long long*)dsm_raw)[e] = ((const unsigned long long*)g_wh)[e];
    __syncthreads();

    if (idx >= NPOSOUT) return;
    const int b = idx / (HH * WW);
    const int hw = idx % (HH * WW);
    const float* fp = g_feat + (size_t)b * IN_CH * (HH * WW) + hw;

    unsigned long long acc[24];
    #pragma unroll
    for (int q = 0; q < 24; q++) acc[q] = 0ull;

    #pragma unroll 2
    for (int ci = 0; ci < IN_CH; ci++) {
        float v = fp[(size_t)ci * (HH * WW)];
        unsigned long long vv = pk2(v, v);
        const unsigned long long* wr = sw2[ci];
        #pragma unroll
        for (int q = 0; q < 24; q++) fma2(acc[q], vv, wr[q]);
    }

    float s[48];
    #pragma unroll
    for (int q = 0; q < 24; q++) upk2(acc[q], s[2 * q], s[2 * q + 1]);

    #pragma unroll
    for (int co = 0; co < NA; co++)
        out[((size_t)(b * NA + co)) * (HH * WW) + hw] = s[co] + bcls[co];
    float* outb = out + (size_t)BATCH * NA * (HH * WW);
    #pragma unroll
    for (int j = 0; j < 36; j++)
        outb[((size_t)(b * 36 + j)) * (HH * WW) + hw] = s[NA + j] + bbbox[j];
}

// ---------------- launch ----------------
extern "C" void kernel_launch(void* const* d_in, const int* in_sizes, int n_in,
                              void* d_out, int out_size) {
    const float* x      = (const float*)d_in[0];
    const float* w_rpn  = (const float*)d_in[1];
    const float* b_rpn  = (const float*)d_in[2];
    const float* w_cls  = (const float*)d_in[3];
    const float* b_cls  = (const float*)d_in[4];
    const float* w_bbox = (const float*)d_in[5];
    const float* b_bbox = (const float*)d_in[6];
    float* out = (float*)d_out;

    cudaFuncSetAttribute(gemm_mma,     cudaFuncAttributeMaxDynamicSharedMemorySize, GEMM_SMEM);
    cudaFuncSetAttribute(xsplit_fused, cudaFuncAttributeMaxDynamicSharedMemorySize, XS_SMEM);
    cudaFuncSetAttribute(heads_kernel, cudaFuncAttributeMaxDynamicSharedMemorySize, HEADS_SMEM);

    wt_kernel<<<(IN_CH * IN_CH + 255) / 256, 256>>>(w_rpn);
    transform_whead<<<(IN_CH * NHEADP + 255) / 256, 256>>>(w_cls, w_bbox);
    xsplit_fused<<<dim3(50, 16, BATCH), 256, XS_SMEM>>>(x);

    gemm_mma<<<dim3(IN_CH / BM, TBLK, NU), 256, GEMM_SMEM>>>();

    inv_kernel<<<(IN_CH * NTILES + 255) / 256, 256>>>(b_rpn);

    heads_kernel<<<(NPOSOUT + 255) / 256, 256, HEADS_SMEM>>>(b_cls, b_bbox, out);
}

// round 15
// speedup vs baseline: 1.2096x; 1.0793x over previous
#include <cuda_runtime.h>
#include <cuda_fp16.h>
#include <cstdint>

#define IN_CH 512
#define BATCH 8
#define HH 100
#define WW 100
#define NA 9
#define NHEAD 45
#define NHEADP 48
#define NPOSOUT 80000                // BATCH*HH*WW

#define PW 102                       // padded grid width/height
#define NPOS (PW * PW)               // 10404 padded positions per batch
#define TPB 2500                     // 50x50 2x2-output tiles per batch
#define NTILES 20000                 // BATCH * TPB
#define TPAD 20096                   // 157 * 128 (tile-dim padded for staging)
#define NU 16                        // winograd coordinates (4x4)

#define BM 128                       // co per CTA
#define BN 128                       // tiles per CTA
#define TBLK 157                     // ceil(NTILES/BN)

// GEMM smem: 3 stages x (Whi 16K | Xhi 16K)
#define OFF_WHI 0
#define OFF_XHI 16384
#define STAGE_BYTES 32768
#define NSTAGE 3
#define GEMM_SMEM (NSTAGE * STAGE_BYTES)     // 98304
#define HEADS_SMEM (512 * 24 * 8)            // 98304

// ---------------- device scratch (allocation-free) ----------------
__device__ float g_feat[BATCH * IN_CH * HH * WW];               // fp32 feature map
__device__ float g_xpad[(size_t)BATCH * NPOS * IN_CH];          // padded channels-last x (fp32)
__device__ __half g_xthi[(size_t)NU * TPAD * IN_CH];            // winograd input (fp16)
__device__ __half g_wthi[(size_t)NU * IN_CH * IN_CH];           // winograd weights [u][co][ci]
__device__ float g_M[(size_t)NU * IN_CH * TPAD];                // transformed-domain products
__device__ float g_wh[IN_CH * NHEADP];                          // head weights [ci][co48]

extern __shared__ char dsm_raw[];

// ---------------- PTX helpers ----------------
__device__ __forceinline__ uint32_t smem_u32(const void* p) {
    uint32_t a;
    asm("{ .reg .u64 t; cvta.to.shared.u64 t, %1; cvt.u32.u64 %0, t; }" : "=r"(a) : "l"(p));
    return a;
}
__device__ __forceinline__ void cp16(uint32_t sdst, const void* gsrc) {
    asm volatile("cp.async.cg.shared.global [%0], [%1], 16;" :: "r"(sdst), "l"(gsrc) : "memory");
}
#define CP_COMMIT() asm volatile("cp.async.commit_group;" ::: "memory")
#define CP_WAIT(n)  asm volatile("cp.async.wait_group %0;" :: "n"(n) : "memory")

__device__ __forceinline__ void ldsm4(uint32_t* r, uint32_t addr) {
    asm volatile("ldmatrix.sync.aligned.m8n8.x4.shared.b16 {%0,%1,%2,%3}, [%4];"
        : "=r"(r[0]), "=r"(r[1]), "=r"(r[2]), "=r"(r[3]) : "r"(addr));
}
__device__ __forceinline__ void mma_f32(float* d, const uint32_t* a, const uint32_t* b) {
    asm volatile(
        "mma.sync.aligned.m16n8k16.row.col.f32.f16.f16.f32 "
        "{%0,%1,%2,%3}, {%4,%5,%6,%7}, {%8,%9}, {%0,%1,%2,%3};"
        : "+f"(d[0]), "+f"(d[1]), "+f"(d[2]), "+f"(d[3])
        : "r"(a[0]), "r"(a[1]), "r"(a[2]), "r"(a[3]), "r"(b[0]), "r"(b[1]));
}
__device__ __forceinline__ uint32_t swz(uint32_t off) { return off ^ ((off >> 3) & 0x70); }

// packed fp32x2 (verified R2/R12)
__device__ __forceinline__ unsigned long long pk2(float x, float y) {
    unsigned long long r;
    asm("mov.b64 %0, {%1, %2};" : "=l"(r) : "r"(__float_as_int(x)), "r"(__float_as_int(y)));
    return r;
}
__device__ __forceinline__ void upk2(unsigned long long v, float& x, float& y) {
    int a, b;
    asm("mov.b64 {%0, %1}, %2;" : "=r"(a), "=r"(b) : "l"(v));
    x = __int_as_float(a); y = __int_as_float(b);
}
__device__ __forceinline__ void fma2(unsigned long long& d, unsigned long long a, unsigned long long b) {
    asm("fma.rn.f32x2 %0, %1, %2, %0;" : "+l"(d) : "l"(a), "l"(b));
}

// ---------------- weight winograd transform (verified R10-R14) ----------------
__global__ void wt_kernel(const float* __restrict__ w) {
    int idx = blockIdx.x * blockDim.x + threadIdx.x;
    if (idx >= IN_CH * IN_CH) return;
    int co = idx / IN_CH, ci = idx % IN_CH;
    const float* wp = w + (size_t)idx * 9;
    float a[3][3];
    #pragma unroll
    for (int r = 0; r < 3; r++)
        #pragma unroll
        for (int c = 0; c < 3; c++) a[r][c] = wp[r * 3 + c];
    float u[4][3];
    #pragma unroll
    for (int c = 0; c < 3; c++) {
        u[0][c] = a[0][c];
        u[1][c] = 0.5f * (a[0][c] + a[1][c] + a[2][c]);
        u[2][c] = 0.5f * (a[0][c] - a[1][c] + a[2][c]);
        u[3][c] = a[2][c];
    }
    #pragma unroll
    for (int r = 0; r < 4; r++) {
        float t0 = u[r][0], t1 = u[r][1], t2 = u[r][2];
        float v[4] = { t0, 0.5f * (t0 + t1 + t2), 0.5f * (t0 - t1 + t2), t2 };
        #pragma unroll
        for (int s = 0; s < 4; s++)
            g_wthi[((size_t)(r * 4 + s) * IN_CH + co) * IN_CH + ci] = __float2half_rn(v[s]);
    }
}

__global__ void transform_whead(const float* __restrict__ wcls, const float* __restrict__ wbbox) {
    int idx = blockIdx.x * blockDim.x + threadIdx.x;
    if (idx >= IN_CH * NHEADP) return;
    int co = idx % NHEADP, ci = idx / NHEADP;
    float v = 0.0f;
    if (co < NA)         v = wcls[co * IN_CH + ci];
    else if (co < NHEAD) v = wbbox[(co - NA) * IN_CH + ci];
    g_wh[idx] = v;
}

// ---------------- padded channels-last fp32 x (exact R12 version) ----------------
__global__ void xpad_kernel(const float* __restrict__ x) {
    __shared__ float tile[32][33];
    int xc = blockIdx.x, y = blockIdx.y, b = blockIdx.z;
    int x0 = xc * 32;
    for (int cc0 = 0; cc0 < IN_CH; cc0 += 32) {
        #pragma unroll
        for (int it = 0; it < 4; it++) {
            int ci = cc0 + threadIdx.y + it * 8;
            int xx = x0 + threadIdx.x;
            float v = 0.0f;
            if (xx < WW) v = x[(((size_t)b * IN_CH + ci) * HH + y) * WW + xx];
            tile[threadIdx.y + it * 8][threadIdx.x] = v;
        }
        __syncthreads();
        #pragma unroll
        for (int j = 0; j < 4; j++) {
            int xl = threadIdx.y * 4 + j;
            int xx = x0 + xl;
            if (xx < WW) {
                size_t row = (size_t)b * NPOS + (size_t)(y + 1) * PW + (xx + 1);
                g_xpad[row * IN_CH + cc0 + threadIdx.x] = tile[threadIdx.x][xl];
            }
        }
        __syncthreads();
    }
}

__global__ void xborder_kernel() {
    int idx = blockIdx.x * blockDim.x + threadIdx.x;
    if (idx >= BATCH * 404 * IN_CH) return;
    int b = idx / (404 * IN_CH);
    int r = idx % (404 * IN_CH);
    int bp = r / IN_CH, ci = r % IN_CH;
    int p;
    if (bp < 102)       p = bp;
    else if (bp < 204)  p = 101 * PW + (bp - 102);
    else { int q = bp - 204; p = (1 + q / 2) * PW + ((q & 1) ? 101 : 0); }
    g_xpad[((size_t)b * NPOS + p) * IN_CH + ci] = 0.0f;
}

// ---------------- input winograd transform: rolling 4-row window (exact R12) ----------------
// grid (50 tx, 5 ty-segments, 8 b), block 256 = ci-pairs (512 ci)
__global__ __launch_bounds__(256)
void xt_kernel() {
    const int ci  = threadIdx.x * 2;
    const int tx  = blockIdx.x;
    const int seg = blockIdx.y;
    const int b   = blockIdx.z;
    const size_t base = ((size_t)b * NPOS + 2 * tx) * IN_CH + ci;

    float2 d[4][4];
    #pragma unroll
    for (int rr = 0; rr < 2; rr++)
        #pragma unroll
        for (int c = 0; c < 4; c++)
            d[2 + rr][c] = *(const float2*)&g_xpad[base + ((size_t)(seg * 20 + rr) * PW + c) * IN_CH];

    for (int j = 0; j < 10; j++) {
        const int ty = seg * 10 + j;
        #pragma unroll
        for (int c = 0; c < 4; c++) { d[0][c] = d[2][c]; d[1][c] = d[3][c]; }
        #pragma unroll
        for (int rr = 0; rr < 2; rr++)
            #pragma unroll
            for (int c = 0; c < 4; c++)
                d[2 + rr][c] = *(const float2*)&g_xpad[base + ((size_t)(2 * ty + 2 + rr) * PW + c) * IN_CH];

        float2 t[4][4];
        #pragma unroll
        for (int c = 0; c < 4; c++) {
            t[0][c] = make_float2(d[0][c].x - d[2][c].x, d[0][c].y - d[2][c].y);
            t[1][c] = make_float2(d[1][c].x + d[2][c].x, d[1][c].y + d[2][c].y);
            t[2][c] = make_float2(d[2][c].x - d[1][c].x, d[2][c].y - d[1][c].y);
            t[3][c] = make_float2(d[1][c].x - d[3][c].x, d[1][c].y - d[3][c].y);
        }
        const int tile = b * TPB + ty * 50 + tx;
        #pragma unroll
        for (int r = 0; r < 4; r++) {
            float2 v[4];
            v[0] = make_float2(t[r][0].x - t[r][2].x, t[r][0].y - t[r][2].y);
            v[1] = make_float2(t[r][1].x + t[r][2].x, t[r][1].y + t[r][2].y);
            v[2] = make_float2(t[r][2].x - t[r][1].x, t[r][2].y - t[r][1].y);
            v[3] = make_float2(t[r][1].x - t[r][3].x, t[r][1].y - t[r][3].y);
            #pragma unroll
            for (int s = 0; s < 4; s++) {
                int uu = r * 4 + s;
                size_t o = ((size_t)uu * TPAD + tile) * IN_CH + ci;
                *(__half2*)&g_xthi[o] =
                    __halves2half2(__float2half_rn(v[s].x), __float2half_rn(v[s].y));
            }
        }
    }
}

// ---------------- winograd-domain GEMM: u-paired (2 coordinates per CTA) ----------------
__global__ __launch_bounds__(256, 2)
void gemm_mma() {
    const uint32_t base = smem_u32(dsm_raw);
    const int tid  = threadIdx.x;
    const int lane = tid & 31;
    const int wid  = tid >> 5;
    const int wm   = wid & 1;
    const int wn   = wid >> 1;
    const int co0  = blockIdx.x * BM;
    const int p0   = blockIdx.y * BN;
    const int up   = blockIdx.z;          // u pair: handles u = 2*up and 2*up+1

    float acc[4][4][4];
    #pragma unroll
    for (int mt = 0; mt < 4; mt++)
        #pragma unroll
        for (int nt = 0; nt < 4; nt++)
            #pragma unroll
            for (int i = 0; i < 4; i++) acc[mt][nt][i] = 0.0f;

    const int arowoff = lane & 15;
    const int ahalf   = lane >> 4;
    const int browoff = (lane & 7) + ((lane >> 4) << 3);
    const int bhalf   = (lane >> 3) & 1;
    const int l7      = lane & 7;

    uint32_t aoff[4];
    #pragma unroll
    for (int mt = 0; mt < 4; mt++) aoff[mt] = (uint32_t)(wm * 64 + mt * 16 + arowoff) * 128u;
    uint32_t boff[2];
    #pragma unroll
    for (int np = 0; np < 2; np++) boff[np] = (uint32_t)(wn * 32 + np * 16 + browoff) * 128u;

    // chunk 0..15: u = 2*up + (chunk>>3), kc = chunk&7  (8 k-chunks per u)
    auto stage = [&](int chunk, uint32_t sb) {
        const int u  = 2 * up + (chunk >> 3);
        const int kc = chunk & 7;
        const __half* whi = g_wthi + (size_t)u * IN_CH * IN_CH;
        const __half* xhi = g_xthi + (size_t)u * TPAD * IN_CH;
        #pragma unroll
        for (int i = 0; i < 4; i++) {
            int e = i * 256 + tid;
            int rr = e >> 3, cc = e & 7;
            uint32_t so = swz((uint32_t)(rr * 128 + cc * 16));
            size_t gw = (size_t)(co0 + rr) * IN_CH + kc * 64 + cc * 8;
            size_t gx = (size_t)(p0 + rr) * IN_CH + kc * 64 + cc * 8;
            cp16(sb + OFF_WHI + so, whi + gw);
            cp16(sb + OFF_XHI + so, xhi + gx);
        }
        CP_COMMIT();
    };

    stage(0, base);
    stage(1, base + STAGE_BYTES);

    #pragma unroll 1
    for (int chunk = 0; chunk < 16; chunk++) {
        if (chunk + 2 < 16) { CP_WAIT(1); } else { CP_WAIT(0); }
        __syncthreads();
        if (chunk + 2 < 16)
            stage(chunk + 2, base + (uint32_t)((chunk + 2) % NSTAGE) * STAGE_BYTES);

        const uint32_t sb = base + (uint32_t)(chunk % NSTAGE) * STAGE_BYTES;
        #pragma unroll
        for (int ks = 0; ks < 4; ks++) {
            const uint32_t acol = (uint32_t)((2 * ks + ahalf) ^ l7) << 4;
            const uint32_t bcol = (uint32_t)((2 * ks + bhalf) ^ l7) << 4;
            uint32_t ah[4][4], bh[2][4];
            #pragma unroll
            for (int mt = 0; mt < 4; mt++)
                ldsm4(ah[mt], sb + OFF_WHI + aoff[mt] + acol);
            #pragma unroll
            for (int np = 0; np < 2; np++)
                ldsm4(bh[np], sb + OFF_XHI + boff[np] + bcol);
            #pragma unroll
            for (int mt = 0; mt < 4; mt++)
                #pragma unroll
                for (int nt = 0; nt < 4; nt++)
                    mma_f32(acc[mt][nt], ah[mt], &bh[nt >> 1][(nt & 1) * 2]);
        }

        // u complete at chunk 7 (u=2up) and 15 (u=2up+1): store + reset
        if ((chunk & 7) == 7) {
            const int u = 2 * up + (chunk >> 3);
            #pragma unroll
            for (int mt = 0; mt < 4; mt++) {
                const int r0 = co0 + wm * 64 + mt * 16 + (lane >> 2);
                const size_t mb0 = ((size_t)u * IN_CH + r0) * TPAD;
                const size_t mb1 = ((size_t)u * IN_CH + r0 + 8) * TPAD;
                #pragma unroll
                for (int nt = 0; nt < 4; nt++) {
                    const int p = p0 + wn * 32 + nt * 8 + ((lane & 3) << 1);
                    *(float2*)&g_M[mb0 + p] = make_float2(acc[mt][nt][0], acc[mt][nt][1]);
                    *(float2*)&g_M[mb1 + p] = make_float2(acc[mt][nt][2], acc[mt][nt][3]);
                    #pragma unroll
                    for (int i = 0; i < 4; i++) acc[mt][nt][i] = 0.0f;
                }
            }
        }
    }
}

// ---------------- inverse transform (exact R12 version) ----------------
__global__ __launch_bounds__(256)
void inv_kernel(const float* __restrict__ brpn) {
    const int idx = blockIdx.x * 256 + threadIdx.x;
    if (idx >= IN_CH * NTILES) return;
    const int co   = idx / NTILES;
    const int tile = idx - co * NTILES;
    const int b  = tile / TPB;
    const int t2 = tile - b * TPB;
    const int ty = t2 / 50;
    const int tx = t2 - ty * 50;

    float m[4][4];
    #pragma unroll
    for (int r = 0; r < 4; r++)
        #pragma unroll
        for (int s = 0; s < 4; s++)
            m[r][s] = g_M[((size_t)(r * 4 + s) * IN_CH + co) * TPAD + tile];

    float t0[4], t1[4];
    #pragma unroll
    for (int s = 0; s < 4; s++) {
        t0[s] = m[0][s] + m[1][s] + m[2][s];
        t1[s] = m[1][s] - m[2][s] - m[3][s];
    }
    const float bv = brpn[co];
    float o00 = t0[0] + t0[1] + t0[2] + bv;
    float o01 = t0[1] - t0[2] - t0[3] + bv;
    float o10 = t1[0] + t1[1] + t1[2] + bv;
    float o11 = t1[1] - t1[2] - t1[3] + bv;

    float* fb = g_feat + ((size_t)(b * IN_CH + co)) * (HH * WW) + (size_t)(2 * ty) * WW + 2 * tx;
    *(float2*)fb        = make_float2(fmaxf(o00, 0.0f), fmaxf(o01, 0.0f));
    *(float2*)(fb + WW) = make_float2(fmaxf(o10, 0.0f), fmaxf(o11, 0.0f));
}

// ---------------- FUSED heads (R13/R14): single kernel, FFMA2 co-pairs ----------------
__global__ __launch_bounds__(256)
void heads_kernel(const float* __restrict__ bcls, const float* __restrict__ bbbox,
                  float* __restrict__ out) {
    unsigned long long (*sw2)[24] = (unsigned long long(*)[24])dsm_raw;
    const int idx = blockIdx.x * 256 + threadIdx.x;

    for (int e = threadIdx.x; e < 512 * 24; e += 256)
        ((unsigned long long*)dsm_raw)[e] = ((const unsigned long long*)g_wh)[e];
    __syncthreads();

    if (idx >= NPOSOUT) return;
    const int b = idx / (HH * WW);
    const int hw = idx % (HH * WW);
    const float* fp = g_feat + (size_t)b * IN_CH * (HH * WW) + hw;

    unsigned long long acc[24];
    #pragma unroll
    for (int q = 0; q < 24; q++) acc[q] = 0ull;

    #pragma unroll 2
    for (int ci = 0; ci < IN_CH; ci++) {
        float v = fp[(size_t)ci * (HH * WW)];
        unsigned long long vv = pk2(v, v);
        const unsigned long long* wr = sw2[ci];
        #pragma unroll
        for (int q = 0; q < 24; q++) fma2(acc[q], vv, wr[q]);
    }

    float s[48];
    #pragma unroll
    for (int q = 0; q < 24; q++) upk2(acc[q], s[2 * q], s[2 * q + 1]);

    #pragma unroll
    for (int co = 0; co < NA; co++)
        out[((size_t)(b * NA + co)) * (HH * WW) + hw] = s[co] + bcls[co];
    float* outb = out + (size_t)BATCH * NA * (HH * WW);
    #pragma unroll
    for (int j = 0; j < 36; j++)
        outb[((size_t)(b * 36 + j)) * (HH * WW) + hw] = s[NA + j] + bbbox[j];
}

// ---------------- launch ----------------
extern "C" void kernel_launch(void* const* d_in, const int* in_sizes, int n_in,
                              void* d_out, int out_size) {
    const float* x      = (const float*)d_in[0];
    const float* w_rpn  = (const float*)d_in[1];
    const float* b_rpn  = (const float*)d_in[2];
    const float* w_cls  = (const float*)d_in[3];
    const float* b_cls  = (const float*)d_in[4];
    const float* w_bbox = (const float*)d_in[5];
    const float* b_bbox = (const float*)d_in[6];
    float* out = (float*)d_out;

    cudaFuncSetAttribute(gemm_mma,     cudaFuncAttributeMaxDynamicSharedMemorySize, GEMM_SMEM);
    cudaFuncSetAttribute(heads_kernel, cudaFuncAttributeMaxDynamicSharedMemorySize, HEADS_SMEM);

    wt_kernel<<<(IN_CH * IN_CH + 255) / 256, 256>>>(w_rpn);
    transform_whead<<<(IN_CH * NHEADP + 255) / 256, 256>>>(w_cls, w_bbox);
    xborder_kernel<<<(BATCH * 404 * IN_CH + 255) / 256, 256>>>();
    xpad_kernel<<<dim3(4, HH, BATCH), dim3(32, 8)>>>(x);
    xt_kernel<<<dim3(50, 5, BATCH), 256>>>();

    gemm_mma<<<dim3(IN_CH / BM, TBLK, NU / 2), 256, GEMM_SMEM>>>();

    inv_kernel<<<(IN_CH * NTILES + 255) / 256, 256>>>(b_rpn);

    heads_kernel<<<(NPOSOUT + 255) / 256, 256, HEADS_SMEM>>>(b_cls, b_bbox, out);
}

// round 16
// speedup vs baseline: 1.3825x; 1.1429x over previous
#include <cuda_runtime.h>
#include <cuda_fp16.h>
#include <cstdint>

#define IN_CH 512
#define BATCH 8
#define HH 100
#define WW 100
#define NA 9
#define NHEAD 45
#define NHEADP 48
#define NPOSOUT 80000                // BATCH*HH*WW

#define PW 102                       // padded grid width/height
#define NPOS (PW * PW)               // 10404 padded positions per batch
#define TPB 2500                     // 50x50 2x2-output tiles per batch
#define NTILES 20000                 // BATCH * TPB
#define TPAD 20096                   // 157 * 128 (tile-dim padded for staging)
#define NU 16                        // winograd coordinates (4x4)

#define BM 128                       // co per CTA
#define BN 128                       // tiles per CTA
#define TBLK 157                     // ceil(NTILES/BN)

// GEMM smem: 3 stages x (Whi 16K | Xhi 16K)
#define OFF_WHI 0
#define OFF_XHI 16384
#define STAGE_BYTES 32768
#define NSTAGE 3
#define GEMM_SMEM (NSTAGE * STAGE_BYTES)     // 98304

// ---------------- device scratch (allocation-free) ----------------
__device__ float g_feat[BATCH * IN_CH * HH * WW];               // fp32 feature map
__device__ float g_xpad[(size_t)BATCH * NPOS * IN_CH];          // padded channels-last x (fp32)
__device__ __half g_xthi[(size_t)NU * TPAD * IN_CH];            // winograd input (fp16)
__device__ __half g_wthi[(size_t)NU * IN_CH * IN_CH];           // winograd weights [u][co][ci]
__device__ float g_M[(size_t)NU * IN_CH * TPAD];                // transformed-domain products
__device__ float g_wh[IN_CH * NHEADP];                          // head weights [ci][co48]
__device__ float g_part[4 * NHEAD * NPOSOUT];                   // head partials [c][co][pos]

extern __shared__ char dsm_raw[];

// ---------------- PTX helpers ----------------
__device__ __forceinline__ uint32_t smem_u32(const void* p) {
    uint32_t a;
    asm("{ .reg .u64 t; cvta.to.shared.u64 t, %1; cvt.u32.u64 %0, t; }" : "=r"(a) : "l"(p));
    return a;
}
__device__ __forceinline__ void cp16(uint32_t sdst, const void* gsrc) {
    asm volatile("cp.async.cg.shared.global [%0], [%1], 16;" :: "r"(sdst), "l"(gsrc) : "memory");
}
#define CP_COMMIT() asm volatile("cp.async.commit_group;" ::: "memory")
#define CP_WAIT(n)  asm volatile("cp.async.wait_group %0;" :: "n"(n) : "memory")

__device__ __forceinline__ void ldsm4(uint32_t* r, uint32_t addr) {
    asm volatile("ldmatrix.sync.aligned.m8n8.x4.shared.b16 {%0,%1,%2,%3}, [%4];"
        : "=r"(r[0]), "=r"(r[1]), "=r"(r[2]), "=r"(r[3]) : "r"(addr));
}
__device__ __forceinline__ void mma_f32(float* d, const uint32_t* a, const uint32_t* b) {
    asm volatile(
        "mma.sync.aligned.m16n8k16.row.col.f32.f16.f16.f32 "
        "{%0,%1,%2,%3}, {%4,%5,%6,%7}, {%8,%9}, {%0,%1,%2,%3};"
        : "+f"(d[0]), "+f"(d[1]), "+f"(d[2]), "+f"(d[3])
        : "r"(a[0]), "r"(a[1]), "r"(a[2]), "r"(a[3]), "r"(b[0]), "r"(b[1]));
}
__device__ __forceinline__ uint32_t swz(uint32_t off) { return off ^ ((off >> 3) & 0x70); }

// packed fp32x2 (verified R2/R12)
__device__ __forceinline__ unsigned long long pk2(float x, float y) {
    unsigned long long r;
    asm("mov.b64 %0, {%1, %2};" : "=l"(r) : "r"(__float_as_int(x)), "r"(__float_as_int(y)));
    return r;
}
__device__ __forceinline__ void upk2(unsigned long long v, float& x, float& y) {
    int a, b;
    asm("mov.b64 {%0, %1}, %2;" : "=r"(a), "=r"(b) : "l"(v));
    x = __int_as_float(a); y = __int_as_float(b);
}
__device__ __forceinline__ void fma2(unsigned long long& d, unsigned long long a, unsigned long long b) {
    asm("fma.rn.f32x2 %0, %1, %2, %0;" : "+l"(d) : "l"(a), "l"(b));
}

// ---------------- weight winograd transform (verified R10-R15) ----------------
__global__ void wt_kernel(const float* __restrict__ w) {
    int idx = blockIdx.x * blockDim.x + threadIdx.x;
    if (idx >= IN_CH * IN_CH) return;
    int co = idx / IN_CH, ci = idx % IN_CH;
    const float* wp = w + (size_t)idx * 9;
    float a[3][3];
    #pragma unroll
    for (int r = 0; r < 3; r++)
        #pragma unroll
        for (int c = 0; c < 3; c++) a[r][c] = wp[r * 3 + c];
    float u[4][3];
    #pragma unroll
    for (int c = 0; c < 3; c++) {
        u[0][c] = a[0][c];
        u[1][c] = 0.5f * (a[0][c] + a[1][c] + a[2][c]);
        u[2][c] = 0.5f * (a[0][c] - a[1][c] + a[2][c]);
        u[3][c] = a[2][c];
    }
    #pragma unroll
    for (int r = 0; r < 4; r++) {
        float t0 = u[r][0], t1 = u[r][1], t2 = u[r][2];
        float v[4] = { t0, 0.5f * (t0 + t1 + t2), 0.5f * (t0 - t1 + t2), t2 };
        #pragma unroll
        for (int s = 0; s < 4; s++)
            g_wthi[((size_t)(r * 4 + s) * IN_CH + co) * IN_CH + ci] = __float2half_rn(v[s]);
    }
}

__global__ void transform_whead(const float* __restrict__ wcls, const float* __restrict__ wbbox) {
    int idx = blockIdx.x * blockDim.x + threadIdx.x;
    if (idx >= IN_CH * NHEADP) return;
    int co = idx % NHEADP, ci = idx / NHEADP;
    float v = 0.0f;
    if (co < NA)         v = wcls[co * IN_CH + ci];
    else if (co < NHEAD) v = wbbox[(co - NA) * IN_CH + ci];
    g_wh[idx] = v;
}

// ---------------- padded channels-last fp32 x (exact R12) ----------------
__global__ void xpad_kernel(const float* __restrict__ x) {
    __shared__ float tile[32][33];
    int xc = blockIdx.x, y = blockIdx.y, b = blockIdx.z;
    int x0 = xc * 32;
    for (int cc0 = 0; cc0 < IN_CH; cc0 += 32) {
        #pragma unroll
        for (int it = 0; it < 4; it++) {
            int ci = cc0 + threadIdx.y + it * 8;
            int xx = x0 + threadIdx.x;
            float v = 0.0f;
            if (xx < WW) v = x[(((size_t)b * IN_CH + ci) * HH + y) * WW + xx];
            tile[threadIdx.y + it * 8][threadIdx.x] = v;
        }
        __syncthreads();
        #pragma unroll
        for (int j = 0; j < 4; j++) {
            int xl = threadIdx.y * 4 + j;
            int xx = x0 + xl;
            if (xx < WW) {
                size_t row = (size_t)b * NPOS + (size_t)(y + 1) * PW + (xx + 1);
                g_xpad[row * IN_CH + cc0 + threadIdx.x] = tile[threadIdx.x][xl];
            }
        }
        __syncthreads();
    }
}

__global__ void xborder_kernel() {
    int idx = blockIdx.x * blockDim.x + threadIdx.x;
    if (idx >= BATCH * 404 * IN_CH) return;
    int b = idx / (404 * IN_CH);
    int r = idx % (404 * IN_CH);
    int bp = r / IN_CH, ci = r % IN_CH;
    int p;
    if (bp < 102)       p = bp;
    else if (bp < 204)  p = 101 * PW + (bp - 102);
    else { int q = bp - 204; p = (1 + q / 2) * PW + ((q & 1) ? 101 : 0); }
    g_xpad[((size_t)b * NPOS + p) * IN_CH + ci] = 0.0f;
}

// ---------------- input winograd transform: rolling 4-row window (exact R12) ----------------
__global__ __launch_bounds__(256)
void xt_kernel() {
    const int ci  = threadIdx.x * 2;
    const int tx  = blockIdx.x;
    const int seg = blockIdx.y;
    const int b   = blockIdx.z;
    const size_t base = ((size_t)b * NPOS + 2 * tx) * IN_CH + ci;

    float2 d[4][4];
    #pragma unroll
    for (int rr = 0; rr < 2; rr++)
        #pragma unroll
        for (int c = 0; c < 4; c++)
            d[2 + rr][c] = *(const float2*)&g_xpad[base + ((size_t)(seg * 20 + rr) * PW + c) * IN_CH];

    for (int j = 0; j < 10; j++) {
        const int ty = seg * 10 + j;
        #pragma unroll
        for (int c = 0; c < 4; c++) { d[0][c] = d[2][c]; d[1][c] = d[3][c]; }
        #pragma unroll
        for (int rr = 0; rr < 2; rr++)
            #pragma unroll
            for (int c = 0; c < 4; c++)
                d[2 + rr][c] = *(const float2*)&g_xpad[base + ((size_t)(2 * ty + 2 + rr) * PW + c) * IN_CH];

        float2 t[4][4];
        #pragma unroll
        for (int c = 0; c < 4; c++) {
            t[0][c] = make_float2(d[0][c].x - d[2][c].x, d[0][c].y - d[2][c].y);
            t[1][c] = make_float2(d[1][c].x + d[2][c].x, d[1][c].y + d[2][c].y);
            t[2][c] = make_float2(d[2][c].x - d[1][c].x, d[2][c].y - d[1][c].y);
            t[3][c] = make_float2(d[1][c].x - d[3][c].x, d[1][c].y - d[3][c].y);
        }
        const int tile = b * TPB + ty * 50 + tx;
        #pragma unroll
        for (int r = 0; r < 4; r++) {
            float2 v[4];
            v[0] = make_float2(t[r][0].x - t[r][2].x, t[r][0].y - t[r][2].y);
            v[1] = make_float2(t[r][1].x + t[r][2].x, t[r][1].y + t[r][2].y);
            v[2] = make_float2(t[r][2].x - t[r][1].x, t[r][2].y - t[r][1].y);
            v[3] = make_float2(t[r][1].x - t[r][3].x, t[r][1].y - t[r][3].y);
            #pragma unroll
            for (int s = 0; s < 4; s++) {
                int uu = r * 4 + s;
                size_t o = ((size_t)uu * TPAD + tile) * IN_CH + ci;
                *(__half2*)&g_xthi[o] =
                    __halves2half2(__float2half_rn(v[s].x), __float2half_rn(v[s].y));
            }
        }
    }
}

// ---------------- winograd-domain GEMM: 4-u pairing (4 coordinates per CTA) ----------------
__global__ __launch_bounds__(256, 2)
void gemm_mma() {
    const uint32_t base = smem_u32(dsm_raw);
    const int tid  = threadIdx.x;
    const int lane = tid & 31;
    const int wid  = tid >> 5;
    const int wm   = wid & 1;
    const int wn   = wid >> 1;
    const int co0  = blockIdx.x * BM;
    const int p0   = blockIdx.y * BN;
    const int up   = blockIdx.z;          // handles u = 4*up .. 4*up+3

    float acc[4][4][4];
    #pragma unroll
    for (int mt = 0; mt < 4; mt++)
        #pragma unroll
        for (int nt = 0; nt < 4; nt++)
            #pragma unroll
            for (int i = 0; i < 4; i++) acc[mt][nt][i] = 0.0f;

    const int arowoff = lane & 15;
    const int ahalf   = lane >> 4;
    const int browoff = (lane & 7) + ((lane >> 4) << 3);
    const int bhalf   = (lane >> 3) & 1;
    const int l7      = lane & 7;

    uint32_t aoff[4];
    #pragma unroll
    for (int mt = 0; mt < 4; mt++) aoff[mt] = (uint32_t)(wm * 64 + mt * 16 + arowoff) * 128u;
    uint32_t boff[2];
    #pragma unroll
    for (int np = 0; np < 2; np++) boff[np] = (uint32_t)(wn * 32 + np * 16 + browoff) * 128u;

    // chunk 0..31: u = 4*up + (chunk>>3), kc = chunk&7
    auto stage = [&](int chunk, uint32_t sb) {
        const int u  = 4 * up + (chunk >> 3);
        const int kc = chunk & 7;
        const __half* whi = g_wthi + (size_t)u * IN_CH * IN_CH;
        const __half* xhi = g_xthi + (size_t)u * TPAD * IN_CH;
        #pragma unroll
        for (int i = 0; i < 4; i++) {
            int e = i * 256 + tid;
            int rr = e >> 3, cc = e & 7;
            uint32_t so = swz((uint32_t)(rr * 128 + cc * 16));
            size_t gw = (size_t)(co0 + rr) * IN_CH + kc * 64 + cc * 8;
            size_t gx = (size_t)(p0 + rr) * IN_CH + kc * 64 + cc * 8;
            cp16(sb + OFF_WHI + so, whi + gw);
            cp16(sb + OFF_XHI + so, xhi + gx);
        }
        CP_COMMIT();
    };

    stage(0, base);
    stage(1, base + STAGE_BYTES);

    #pragma unroll 1
    for (int chunk = 0; chunk < 32; chunk++) {
        if (chunk + 2 < 32) { CP_WAIT(1); } else { CP_WAIT(0); }
        __syncthreads();
        if (chunk + 2 < 32)
            stage(chunk + 2, base + (uint32_t)((chunk + 2) % NSTAGE) * STAGE_BYTES);

        const uint32_t sb = base + (uint32_t)(chunk % NSTAGE) * STAGE_BYTES;
        #pragma unroll
        for (int ks = 0; ks < 4; ks++) {
            const uint32_t acol = (uint32_t)((2 * ks + ahalf) ^ l7) << 4;
            const uint32_t bcol = (uint32_t)((2 * ks + bhalf) ^ l7) << 4;
            uint32_t ah[4][4], bh[2][4];
            #pragma unroll
            for (int mt = 0; mt < 4; mt++)
                ldsm4(ah[mt], sb + OFF_WHI + aoff[mt] + acol);
            #pragma unroll
            for (int np = 0; np < 2; np++)
                ldsm4(bh[np], sb + OFF_XHI + boff[np] + bcol);
            #pragma unroll
            for (int mt = 0; mt < 4; mt++)
                #pragma unroll
                for (int nt = 0; nt < 4; nt++)
                    mma_f32(acc[mt][nt], ah[mt], &bh[nt >> 1][(nt & 1) * 2]);
        }

        // u complete every 8 chunks: store + reset (bit-exact per-u result)
        if ((chunk & 7) == 7) {
            const int u = 4 * up + (chunk >> 3);
            #pragma unroll
            for (int mt = 0; mt < 4; mt++) {
                const int r0 = co0 + wm * 64 + mt * 16 + (lane >> 2);
                const size_t mb0 = ((size_t)u * IN_CH + r0) * TPAD;
                const size_t mb1 = ((size_t)u * IN_CH + r0 + 8) * TPAD;
                #pragma unroll
                for (int nt = 0; nt < 4; nt++) {
                    const int p = p0 + wn * 32 + nt * 8 + ((lane & 3) << 1);
                    *(float2*)&g_M[mb0 + p] = make_float2(acc[mt][nt][0], acc[mt][nt][1]);
                    *(float2*)&g_M[mb1 + p] = make_float2(acc[mt][nt][2], acc[mt][nt][3]);
                    #pragma unroll
                    for (int i = 0; i < 4; i++) acc[mt][nt][i] = 0.0f;
                }
            }
        }
    }
}

// ---------------- inverse transform (exact R12) ----------------
__global__ __launch_bounds__(256)
void inv_kernel(const float* __restrict__ brpn) {
    const int idx = blockIdx.x * 256 + threadIdx.x;
    if (idx >= IN_CH * NTILES) return;
    const int co   = idx / NTILES;
    const int tile = idx - co * NTILES;
    const int b  = tile / TPB;
    const int t2 = tile - b * TPB;
    const int ty = t2 / 50;
    const int tx = t2 - ty * 50;

    float m[4][4];
    #pragma unroll
    for (int r = 0; r < 4; r++)
        #pragma unroll
        for (int s = 0; s < 4; s++)
            m[r][s] = g_M[((size_t)(r * 4 + s) * IN_CH + co) * TPAD + tile];

    float t0[4], t1[4];
    #pragma unroll
    for (int s = 0; s < 4; s++) {
        t0[s] = m[0][s] + m[1][s] + m[2][s];
        t1[s] = m[1][s] - m[2][s] - m[3][s];
    }
    const float bv = brpn[co];
    float o00 = t0[0] + t0[1] + t0[2] + bv;
    float o01 = t0[1] - t0[2] - t0[3] + bv;
    float o10 = t1[0] + t1[1] + t1[2] + bv;
    float o11 = t1[1] - t1[2] - t1[3] + bv;

    float* fb = g_feat + ((size_t)(b * IN_CH + co)) * (HH * WW) + (size_t)(2 * ty) * WW + 2 * tx;
    *(float2*)fb        = make_float2(fmaxf(o00, 0.0f), fmaxf(o01, 0.0f));
    *(float2*)(fb + WW) = make_float2(fmaxf(o10, 0.0f), fmaxf(o11, 0.0f));
}

// ---------------- heads stage A: FFMA2 co-pairs, 4-way ci split (exact R12) ----------------
__global__ __launch_bounds__(256)
void headsA_kernel() {
    __shared__ unsigned long long sw2[128][24];
    const int c = blockIdx.y;
    const int idx = blockIdx.x * 256 + threadIdx.x;
    const bool active = idx < NPOSOUT;
    const int b = idx / (HH * WW);
    const int hw = idx % (HH * WW);
    const float* fp = g_feat + ((size_t)b * IN_CH + c * 128) * (HH * WW) + hw;

    for (int e = threadIdx.x; e < 128 * 24; e += 256)
        ((unsigned long long*)sw2)[e] =
            ((const unsigned long long*)g_wh)[(size_t)(c * 128) * 24 + e];
    __syncthreads();

    if (!active) return;

    unsigned long long acc[24];
    #pragma unroll
    for (int q = 0; q < 24; q++) acc[q] = 0ull;

    for (int ci = 0; ci < 128; ci++) {
        float v = fp[(size_t)ci * (HH * WW)];
        unsigned long long vv = pk2(v, v);
        const unsigned long long* wr = sw2[ci];
        #pragma unroll
        for (int q = 0; q < 24; q++) fma2(acc[q], vv, wr[q]);
    }

    #pragma unroll
    for (int q = 0; q < 23; q++) {
        float lo, hi;
        upk2(acc[q], lo, hi);
        int co = 2 * q;
        g_part[((size_t)(c * NHEAD + co)) * NPOSOUT + idx] = lo;
        if (co + 1 < NHEAD)
            g_part[((size_t)(c * NHEAD + co + 1)) * NPOSOUT + idx] = hi;
    }
}

// ---------------- heads stage B (exact R12) ----------------
__global__ __launch_bounds__(256)
void headsB_kernel(const float* __restrict__ bcls, const float* __restrict__ bbbox,
                   float* __restrict__ out) {
    const int e = blockIdx.x * 256 + threadIdx.x;
    if (e >= NHEAD * NPOSOUT) return;
    const int co = e / NPOSOUT;
    const int pos = e % NPOSOUT;
    float s = g_part[e]
            + g_part[e + 1 * NHEAD * NPOSOUT]
            + g_part[e + 2 * NHEAD * NPOSOUT]
            + g_part[e + 3 * NHEAD * NPOSOUT];
    const int b = pos / (HH * WW);
    const int hw = pos % (HH * WW);
    if (co < NA) {
        out[((size_t)(b * NA + co)) * (HH * WW) + hw] = s + bcls[co];
    } else {
        const int j = co - NA;
        out[(size_t)BATCH * NA * (HH * WW) + ((size_t)(b * 36 + j)) * (HH * WW) + hw]
            = s + bbbox[j];
    }
}

// ---------------- launch ----------------
extern "C" void kernel_launch(void* const* d_in, const int* in_sizes, int n_in,
                              void* d_out, int out_size) {
    const float* x      = (const float*)d_in[0];
    const float* w_rpn  = (const float*)d_in[1];
    const float* b_rpn  = (const float*)d_in[2];
    const float* w_cls  = (const float*)d_in[3];
    const float* b_cls  = (const float*)d_in[4];
    const float* w_bbox = (const float*)d_in[5];
    const float* b_bbox = (const float*)d_in[6];
    float* out = (float*)d_out;

    cudaFuncSetAttribute(gemm_mma, cudaFuncAttributeMaxDynamicSharedMemorySize, GEMM_SMEM);

    wt_kernel<<<(IN_CH * IN_CH + 255) / 256, 256>>>(w_rpn);
    transform_whead<<<(IN_CH * NHEADP + 255) / 256, 256>>>(w_cls, w_bbox);
    xborder_kernel<<<(BATCH * 404 * IN_CH + 255) / 256, 256>>>();
    xpad_kernel<<<dim3(4, HH, BATCH), dim3(32, 8)>>>(x);
    xt_kernel<<<dim3(50, 5, BATCH), 256>>>();

    gemm_mma<<<dim3(IN_CH / BM, TBLK, NU / 4), 256, GEMM_SMEM>>>();

    inv_kernel<<<(IN_CH * NTILES + 255) / 256, 256>>>(b_rpn);

    headsA_kernel<<<dim3((NPOSOUT + 255) / 256, 4), 256>>>();
    headsB_kernel<<<(NHEAD * NPOSOUT + 255) / 256, 256>>>(b_cls, b_bbox, out);
}

// round 17
// speedup vs baseline: 1.4804x; 1.0709x over previous
#include <cuda_runtime.h>
#include <cuda_fp16.h>
#include <cstdint>

#define IN_CH 512
#define BATCH 8
#define HH 100
#define WW 100
#define NA 9
#define NHEAD 45
#define NHEADP 48
#define NPOSOUT 80000                // BATCH*HH*WW

#define PW 102                       // padded grid width/height
#define NPOS (PW * PW)               // 10404 padded positions per batch
#define TPB 2500                     // 50x50 2x2-output tiles per batch
#define NTILES 20000                 // BATCH * TPB
#define TPAD 20096                   // 157 * 128 (tile-dim padded for staging)
#define NU 16                        // winograd coordinates (4x4)

#define BM 128                       // co per CTA
#define BN 128                       // tiles per CTA
#define TBLK 157                     // ceil(NTILES/BN)
#define NITER 8                      // 512 ci / 64

// GEMM smem: 3 stages x (Whi 16K | Xhi 16K)
#define OFF_WHI 0
#define OFF_XHI 16384
#define STAGE_BYTES 32768
#define NSTAGE 3
#define GEMM_SMEM (NSTAGE * STAGE_BYTES)     // 98304

// ---------------- device scratch (allocation-free) ----------------
__device__ float g_feat[BATCH * IN_CH * HH * WW];               // fp32 feature map
__device__ float g_xpad[(size_t)BATCH * NPOS * IN_CH];          // padded channels-last x (fp32)
__device__ __half g_xthi[(size_t)NU * TPAD * IN_CH];            // winograd input (fp16)
__device__ __half g_wthi[(size_t)NU * IN_CH * IN_CH];           // winograd weights [u][co][ci]
__device__ __half g_M16[(size_t)NU * IN_CH * TPAD];             // transformed-domain products (fp16)
__device__ float g_wh[IN_CH * NHEADP];                          // head weights [ci][co48]
__device__ float g_part[4 * NHEAD * NPOSOUT];                   // head partials [c][co][pos]

extern __shared__ char dsm_raw[];

// ---------------- PTX helpers ----------------
__device__ __forceinline__ uint32_t smem_u32(const void* p) {
    uint32_t a;
    asm("{ .reg .u64 t; cvta.to.shared.u64 t, %1; cvt.u32.u64 %0, t; }" : "=r"(a) : "l"(p));
    return a;
}
__device__ __forceinline__ void cp16(uint32_t sdst, const void* gsrc) {
    asm volatile("cp.async.cg.shared.global [%0], [%1], 16;" :: "r"(sdst), "l"(gsrc) : "memory");
}
#define CP_COMMIT() asm volatile("cp.async.commit_group;" ::: "memory")
#define CP_WAIT(n)  asm volatile("cp.async.wait_group %0;" :: "n"(n) : "memory")

__device__ __forceinline__ void ldsm4(uint32_t* r, uint32_t addr) {
    asm volatile("ldmatrix.sync.aligned.m8n8.x4.shared.b16 {%0,%1,%2,%3}, [%4];"
        : "=r"(r[0]), "=r"(r[1]), "=r"(r[2]), "=r"(r[3]) : "r"(addr));
}
__device__ __forceinline__ void mma_f32(float* d, const uint32_t* a, const uint32_t* b) {
    asm volatile(
        "mma.sync.aligned.m16n8k16.row.col.f32.f16.f16.f32 "
        "{%0,%1,%2,%3}, {%4,%5,%6,%7}, {%8,%9}, {%0,%1,%2,%3};"
        : "+f"(d[0]), "+f"(d[1]), "+f"(d[2]), "+f"(d[3])
        : "r"(a[0]), "r"(a[1]), "r"(a[2]), "r"(a[3]), "r"(b[0]), "r"(b[1]));
}
__device__ __forceinline__ uint32_t swz(uint32_t off) { return off ^ ((off >> 3) & 0x70); }

// packed fp32x2 (verified R2/R12)
__device__ __forceinline__ unsigned long long pk2(float x, float y) {
    unsigned long long r;
    asm("mov.b64 %0, {%1, %2};" : "=l"(r) : "r"(__float_as_int(x)), "r"(__float_as_int(y)));
    return r;
}
__device__ __forceinline__ void upk2(unsigned long long v, float& x, float& y) {
    int a, b;
    asm("mov.b64 {%0, %1}, %2;" : "=r"(a), "=r"(b) : "l"(v));
    x = __int_as_float(a); y = __int_as_float(b);
}
__device__ __forceinline__ void fma2(unsigned long long& d, unsigned long long a, unsigned long long b) {
    asm("fma.rn.f32x2 %0, %1, %2, %0;" : "+l"(d) : "l"(a), "l"(b));
}

// ---------------- weight winograd transform (exact R12) ----------------
__global__ void wt_kernel(const float* __restrict__ w) {
    int idx = blockIdx.x * blockDim.x + threadIdx.x;
    if (idx >= IN_CH * IN_CH) return;
    int co = idx / IN_CH, ci = idx % IN_CH;
    const float* wp = w + (size_t)idx * 9;
    float a[3][3];
    #pragma unroll
    for (int r = 0; r < 3; r++)
        #pragma unroll
        for (int c = 0; c < 3; c++) a[r][c] = wp[r * 3 + c];
    float u[4][3];
    #pragma unroll
    for (int c = 0; c < 3; c++) {
        u[0][c] = a[0][c];
        u[1][c] = 0.5f * (a[0][c] + a[1][c] + a[2][c]);
        u[2][c] = 0.5f * (a[0][c] - a[1][c] + a[2][c]);
        u[3][c] = a[2][c];
    }
    #pragma unroll
    for (int r = 0; r < 4; r++) {
        float t0 = u[r][0], t1 = u[r][1], t2 = u[r][2];
        float v[4] = { t0, 0.5f * (t0 + t1 + t2), 0.5f * (t0 - t1 + t2), t2 };
        #pragma unroll
        for (int s = 0; s < 4; s++)
            g_wthi[((size_t)(r * 4 + s) * IN_CH + co) * IN_CH + ci] = __float2half_rn(v[s]);
    }
}

__global__ void transform_whead(const float* __restrict__ wcls, const float* __restrict__ wbbox) {
    int idx = blockIdx.x * blockDim.x + threadIdx.x;
    if (idx >= IN_CH * NHEADP) return;
    int co = idx % NHEADP, ci = idx / NHEADP;
    float v = 0.0f;
    if (co < NA)         v = wcls[co * IN_CH + ci];
    else if (co < NHEAD) v = wbbox[(co - NA) * IN_CH + ci];
    g_wh[idx] = v;
}

// ---------------- padded channels-last fp32 x (exact R12) ----------------
__global__ void xpad_kernel(const float* __restrict__ x) {
    __shared__ float tile[32][33];
    int xc = blockIdx.x, y = blockIdx.y, b = blockIdx.z;
    int x0 = xc * 32;
    for (int cc0 = 0; cc0 < IN_CH; cc0 += 32) {
        #pragma unroll
        for (int it = 0; it < 4; it++) {
            int ci = cc0 + threadIdx.y + it * 8;
            int xx = x0 + threadIdx.x;
            float v = 0.0f;
            if (xx < WW) v = x[(((size_t)b * IN_CH + ci) * HH + y) * WW + xx];
            tile[threadIdx.y + it * 8][threadIdx.x] = v;
        }
        __syncthreads();
        #pragma unroll
        for (int j = 0; j < 4; j++) {
            int xl = threadIdx.y * 4 + j;
            int xx = x0 + xl;
            if (xx < WW) {
                size_t row = (size_t)b * NPOS + (size_t)(y + 1) * PW + (xx + 1);
                g_xpad[row * IN_CH + cc0 + threadIdx.x] = tile[threadIdx.x][xl];
            }
        }
        __syncthreads();
    }
}

__global__ void xborder_kernel() {
    int idx = blockIdx.x * blockDim.x + threadIdx.x;
    if (idx >= BATCH * 404 * IN_CH) return;
    int b = idx / (404 * IN_CH);
    int r = idx % (404 * IN_CH);
    int bp = r / IN_CH, ci = r % IN_CH;
    int p;
    if (bp < 102)       p = bp;
    else if (bp < 204)  p = 101 * PW + (bp - 102);
    else { int q = bp - 204; p = (1 + q / 2) * PW + ((q & 1) ? 101 : 0); }
    g_xpad[((size_t)b * NPOS + p) * IN_CH + ci] = 0.0f;
}

// ---------------- input winograd transform: rolling 4-row window (exact R12) ----------------
__global__ __launch_bounds__(256)
void xt_kernel() {
    const int ci  = threadIdx.x * 2;
    const int tx  = blockIdx.x;
    const int seg = blockIdx.y;
    const int b   = blockIdx.z;
    const size_t base = ((size_t)b * NPOS + 2 * tx) * IN_CH + ci;

    float2 d[4][4];
    #pragma unroll
    for (int rr = 0; rr < 2; rr++)
        #pragma unroll
        for (int c = 0; c < 4; c++)
            d[2 + rr][c] = *(const float2*)&g_xpad[base + ((size_t)(seg * 20 + rr) * PW + c) * IN_CH];

    for (int j = 0; j < 10; j++) {
        const int ty = seg * 10 + j;
        #pragma unroll
        for (int c = 0; c < 4; c++) { d[0][c] = d[2][c]; d[1][c] = d[3][c]; }
        #pragma unroll
        for (int rr = 0; rr < 2; rr++)
            #pragma unroll
            for (int c = 0; c < 4; c++)
                d[2 + rr][c] = *(const float2*)&g_xpad[base + ((size_t)(2 * ty + 2 + rr) * PW + c) * IN_CH];

        float2 t[4][4];
        #pragma unroll
        for (int c = 0; c < 4; c++) {
            t[0][c] = make_float2(d[0][c].x - d[2][c].x, d[0][c].y - d[2][c].y);
            t[1][c] = make_float2(d[1][c].x + d[2][c].x, d[1][c].y + d[2][c].y);
            t[2][c] = make_float2(d[2][c].x - d[1][c].x, d[2][c].y - d[1][c].y);
            t[3][c] = make_float2(d[1][c].x - d[3][c].x, d[1][c].y - d[3][c].y);
        }
        const int tile = b * TPB + ty * 50 + tx;
        #pragma unroll
        for (int r = 0; r < 4; r++) {
            float2 v[4];
            v[0] = make_float2(t[r][0].x - t[r][2].x, t[r][0].y - t[r][2].y);
            v[1] = make_float2(t[r][1].x + t[r][2].x, t[r][1].y + t[r][2].y);
            v[2] = make_float2(t[r][2].x - t[r][1].x, t[r][2].y - t[r][1].y);
            v[3] = make_float2(t[r][1].x - t[r][3].x, t[r][1].y - t[r][3].y);
            #pragma unroll
            for (int s = 0; s < 4; s++) {
                int uu = r * 4 + s;
                size_t o = ((size_t)uu * TPAD + tile) * IN_CH + ci;
                *(__half2*)&g_xthi[o] =
                    __halves2half2(__float2half_rn(v[s].x), __float2half_rn(v[s].y));
            }
        }
    }
}

// ---------------- winograd-domain GEMM (exact R12 mainloop; fp16 M epilogue) ----------------
__global__ __launch_bounds__(256, 2)
void gemm_mma() {
    const uint32_t base = smem_u32(dsm_raw);
    const int tid  = threadIdx.x;
    const int lane = tid & 31;
    const int wid  = tid >> 5;
    const int wm   = wid & 1;
    const int wn   = wid >> 1;
    const int co0  = blockIdx.x * BM;
    const int p0   = blockIdx.y * BN;
    const int u    = blockIdx.z;

    float acc[4][4][4];
    #pragma unroll
    for (int mt = 0; mt < 4; mt++)
        #pragma unroll
        for (int nt = 0; nt < 4; nt++)
            #pragma unroll
            for (int i = 0; i < 4; i++) acc[mt][nt][i] = 0.0f;

    const int arowoff = lane & 15;
    const int ahalf   = lane >> 4;
    const int browoff = (lane & 7) + ((lane >> 4) << 3);
    const int bhalf   = (lane >> 3) & 1;
    const int l7      = lane & 7;

    uint32_t aoff[4];
    #pragma unroll
    for (int mt = 0; mt < 4; mt++) aoff[mt] = (uint32_t)(wm * 64 + mt * 16 + arowoff) * 128u;
    uint32_t boff[2];
    #pragma unroll
    for (int np = 0; np < 2; np++) boff[np] = (uint32_t)(wn * 32 + np * 16 + browoff) * 128u;

    const __half* whi = g_wthi + (size_t)u * IN_CH * IN_CH;
    const __half* xhi = g_xthi + (size_t)u * TPAD * IN_CH;

    auto stage = [&](int kc, uint32_t sb) {
        #pragma unroll
        for (int i = 0; i < 4; i++) {
            int e = i * 256 + tid;
            int rr = e >> 3, cc = e & 7;
            uint32_t so = swz((uint32_t)(rr * 128 + cc * 16));
            size_t gw = (size_t)(co0 + rr) * IN_CH + kc * 64 + cc * 8;
            size_t gx = (size_t)(p0 + rr) * IN_CH + kc * 64 + cc * 8;
            cp16(sb + OFF_WHI + so, whi + gw);
            cp16(sb + OFF_XHI + so, xhi + gx);
        }
        CP_COMMIT();
    };

    stage(0, base);
    stage(1, base + STAGE_BYTES);

    for (int c = 0; c < NITER; c++) {
        if (c + 2 < NITER) { CP_WAIT(1); } else { CP_WAIT(0); }
        __syncthreads();
        if (c + 2 < NITER)
            stage(c + 2, base + (uint32_t)((c + 2) % NSTAGE) * STAGE_BYTES);

        const uint32_t sb = base + (uint32_t)(c % NSTAGE) * STAGE_BYTES;
        #pragma unroll
        for (int ks = 0; ks < 4; ks++) {
            const uint32_t acol = (uint32_t)((2 * ks + ahalf) ^ l7) << 4;
            const uint32_t bcol = (uint32_t)((2 * ks + bhalf) ^ l7) << 4;
            uint32_t ah[4][4], bh[2][4];
            #pragma unroll
            for (int mt = 0; mt < 4; mt++)
                ldsm4(ah[mt], sb + OFF_WHI + aoff[mt] + acol);
            #pragma unroll
            for (int np = 0; np < 2; np++)
                ldsm4(bh[np], sb + OFF_XHI + boff[np] + bcol);
            #pragma unroll
            for (int mt = 0; mt < 4; mt++)
                #pragma unroll
                for (int nt = 0; nt < 4; nt++)
                    mma_f32(acc[mt][nt], ah[mt], &bh[nt >> 1][(nt & 1) * 2]);
        }
    }

    // epilogue: store M as fp16 pairs (halved traffic vs R12)
    #pragma unroll
    for (int mt = 0; mt < 4; mt++) {
        const int r0 = co0 + wm * 64 + mt * 16 + (lane >> 2);
        const size_t mb0 = ((size_t)u * IN_CH + r0) * TPAD;
        const size_t mb1 = ((size_t)u * IN_CH + r0 + 8) * TPAD;
        #pragma unroll
        for (int nt = 0; nt < 4; nt++) {
            const int p = p0 + wn * 32 + nt * 8 + ((lane & 3) << 1);
            *(__half2*)&g_M16[mb0 + p] =
                __halves2half2(__float2half_rn(acc[mt][nt][0]), __float2half_rn(acc[mt][nt][1]));
            *(__half2*)&g_M16[mb1 + p] =
                __halves2half2(__float2half_rn(acc[mt][nt][2]), __float2half_rn(acc[mt][nt][3]));
        }
    }
}

// ---------------- inverse transform: 2 adjacent tiles/thread, half2 reads, float4 writes ----------------
__global__ __launch_bounds__(256)
void inv_kernel(const float* __restrict__ brpn) {
    const int idx = blockIdx.x * 256 + threadIdx.x;
    if (idx >= IN_CH * (NTILES / 2)) return;
    const int co = idx / (NTILES / 2);
    const int tp = idx - co * (NTILES / 2);
    const int tile0 = 2 * tp;                       // even tx => pair intra-row
    const int b  = tile0 / TPB;
    const int t2 = tile0 - b * TPB;
    const int ty = t2 / 50;
    const int tx = t2 - ty * 50;

    float mA[4][4], mB[4][4];                       // two tiles' 4x4 M
    #pragma unroll
    for (int r = 0; r < 4; r++)
        #pragma unroll
        for (int s = 0; s < 4; s++) {
            __half2 h = *(const __half2*)&g_M16[((size_t)(r * 4 + s) * IN_CH + co) * TPAD + tile0];
            mA[r][s] = __low2float(h);
            mB[r][s] = __high2float(h);
        }

    const float bv = brpn[co];
    float oA[4], oB[4];
    {
        float t0[4], t1[4];
        #pragma unroll
        for (int s = 0; s < 4; s++) {
            t0[s] = mA[0][s] + mA[1][s] + mA[2][s];
            t1[s] = mA[1][s] - mA[2][s] - mA[3][s];
        }
        oA[0] = t0[0] + t0[1] + t0[2] + bv;
        oA[1] = t0[1] - t0[2] - t0[3] + bv;
        oA[2] = t1[0] + t1[1] + t1[2] + bv;
        oA[3] = t1[1] - t1[2] - t1[3] + bv;
    }
    {
        float t0[4], t1[4];
        #pragma unroll
        for (int s = 0; s < 4; s++) {
            t0[s] = mB[0][s] + mB[1][s] + mB[2][s];
            t1[s] = mB[1][s] - mB[2][s] - mB[3][s];
        }
        oB[0] = t0[0] + t0[1] + t0[2] + bv;
        oB[1] = t0[1] - t0[2] - t0[3] + bv;
        oB[2] = t1[0] + t1[1] + t1[2] + bv;
        oB[3] = t1[1] - t1[2] - t1[3] + bv;
    }

    float* fb = g_feat + ((size_t)(b * IN_CH + co)) * (HH * WW) + (size_t)(2 * ty) * WW + 2 * tx;
    float4 r0 = make_float4(fmaxf(oA[0], 0.0f), fmaxf(oA[1], 0.0f),
                            fmaxf(oB[0], 0.0f), fmaxf(oB[1], 0.0f));
    float4 r1 = make_float4(fmaxf(oA[2], 0.0f), fmaxf(oA[3], 0.0f),
                            fmaxf(oB[2], 0.0f), fmaxf(oB[3], 0.0f));
    *(float4*)fb        = r0;
    *(float4*)(fb + WW) = r1;
}

// ---------------- heads stage A: FFMA2 co-pairs, 4-way ci split (exact R12) ----------------
__global__ __launch_bounds__(256)
void headsA_kernel() {
    __shared__ unsigned long long sw2[128][24];
    const int c = blockIdx.y;
    const int idx = blockIdx.x * 256 + threadIdx.x;
    const bool active = idx < NPOSOUT;
    const int b = idx / (HH * WW);
    const int hw = idx % (HH * WW);
    const float* fp = g_feat + ((size_t)b * IN_CH + c * 128) * (HH * WW) + hw;

    for (int e = threadIdx.x; e < 128 * 24; e += 256)
        ((unsigned long long*)sw2)[e] =
            ((const unsigned long long*)g_wh)[(size_t)(c * 128) * 24 + e];
    __syncthreads();

    if (!active) return;

    unsigned long long acc[24];
    #pragma unroll
    for (int q = 0; q < 24; q++) acc[q] = 0ull;

    for (int ci = 0; ci < 128; ci++) {
        float v = fp[(size_t)ci * (HH * WW)];
        unsigned long long vv = pk2(v, v);
        const unsigned long long* wr = sw2[ci];
        #pragma unroll
        for (int q = 0; q < 24; q++) fma2(acc[q], vv, wr[q]);
    }

    #pragma unroll
    for (int q = 0; q < 23; q++) {
        float lo, hi;
        upk2(acc[q], lo, hi);
        int co = 2 * q;
        g_part[((size_t)(c * NHEAD + co)) * NPOSOUT + idx] = lo;
        if (co + 1 < NHEAD)
            g_part[((size_t)(c * NHEAD + co + 1)) * NPOSOUT + idx] = hi;
    }
}

// ---------------- heads stage B (exact R12) ----------------
__global__ __launch_bounds__(256)
void headsB_kernel(const float* __restrict__ bcls, const float* __restrict__ bbbox,
                   float* __restrict__ out) {
    const int e = blockIdx.x * 256 + threadIdx.x;
    if (e >= NHEAD * NPOSOUT) return;
    const int co = e / NPOSOUT;
    const int pos = e % NPOSOUT;
    float s = g_part[e]
            + g_part[e + 1 * NHEAD * NPOSOUT]
            + g_part[e + 2 * NHEAD * NPOSOUT]
            + g_part[e + 3 * NHEAD * NPOSOUT];
    const int b = pos / (HH * WW);
    const int hw = pos % (HH * WW);
    if (co < NA) {
        out[((size_t)(b * NA + co)) * (HH * WW) + hw] = s + bcls[co];
    } else {
        const int j = co - NA;
        out[(size_t)BATCH * NA * (HH * WW) + ((size_t)(b * 36 + j)) * (HH * WW) + hw]
            = s + bbbox[j];
    }
}

// ---------------- launch ----------------
extern "C" void kernel_launch(void* const* d_in, const int* in_sizes, int n_in,
                              void* d_out, int out_size) {
    const float* x      = (const float*)d_in[0];
    const float* w_rpn  = (const float*)d_in[1];
    const float* b_rpn  = (const float*)d_in[2];
    const float* w_cls  = (const float*)d_in[3];
    const float* b_cls  = (const float*)d_in[4];
    const float* w_bbox = (const float*)d_in[5];
    const float* b_bbox = (const float*)d_in[6];
    float* out = (float*)d_out;

    cudaFuncSetAttribute(gemm_mma, cudaFuncAttributeMaxDynamicSharedMemorySize, GEMM_SMEM);

    wt_kernel<<<(IN_CH * IN_CH + 255) / 256, 256>>>(w_rpn);
    transform_whead<<<(IN_CH * NHEADP + 255) / 256, 256>>>(w_cls, w_bbox);
    xborder_kernel<<<(BATCH * 404 * IN_CH + 255) / 256, 256>>>();
    xpad_kernel<<<dim3(4, HH, BATCH), dim3(32, 8)>>>(x);
    xt_kernel<<<dim3(50, 5, BATCH), 256>>>();

    gemm_mma<<<dim3(IN_CH / BM, TBLK, NU), 256, GEMM_SMEM>>>();

    inv_kernel<<<(IN_CH * (NTILES / 2) + 255) / 256, 256>>>(b_rpn);

    headsA_kernel<<<dim3((NPOSOUT + 255) / 256, 4), 256>>>();
    headsB_kernel<<<(NHEAD * NPOSOUT + 255) / 256, 256>>>(b_cls, b_bbox, out);
}